// round 14
// baseline (speedup 1.0000x reference)
#include <cuda_runtime.h>
#include <math.h>

// Problem dims
#define BSZ   64
#define NMEM  512
#define WD    64
#define RH    4
#define OUTD  256
#define IND   256
#define IFC   471     // interface size
#define CD    727     // controller dim
#define G3    2181    // 3*CD

// Output layout offsets (concatenated flattened tuple, f32)
#define OFF_Y      0
#define OFF_MN     16384
#define OFF_USAGE  2113536
#define OFF_LN     2146304
#define OFF_WP     18923520
#define OFF_WR     18956288
#define OFF_WW     19087360
#define OFF_HC     19120128

// Scratch (no cudaMalloc allowed)
__device__ float g_mx[128 * G3];
__device__ float g_mh[128 * G3];
__device__ float g_iface[128 * IFC];
__device__ __align__(16) float g_fwdpart[BSZ * 8 * NMEM * RH];
__device__ __align__(16) float g_bwdpart[BSZ * 8 * NMEM * RH];

__device__ __forceinline__ float sigmoidf_(float x) { return 1.f / (1.f + expf(-x)); }
__device__ __forceinline__ float softplusf_(float x) { return fmaxf(x, 0.f) + log1pf(expf(-fabsf(x))); }

// Block reductions for 512 threads (16 warps)
__device__ __forceinline__ float blk_red_max(float v, float* sb, int t) {
#pragma unroll
    for (int o = 16; o; o >>= 1) v = fmaxf(v, __shfl_xor_sync(0xffffffffu, v, o));
    __syncthreads();
    if ((t & 31) == 0) sb[t >> 5] = v;
    __syncthreads();
    float r = sb[0];
#pragma unroll
    for (int i = 1; i < 16; i++) r = fmaxf(r, sb[i]);
    return r;
}
__device__ __forceinline__ float blk_red_sum(float v, float* sb, int t) {
#pragma unroll
    for (int o = 16; o; o >>= 1) v += __shfl_xor_sync(0xffffffffu, v, o);
    __syncthreads();
    if ((t & 31) == 0) sb[t >> 5] = v;
    __syncthreads();
    float r = 0.f;
#pragma unroll
    for (int i = 0; i < 16; i++) r += sb[i];
    return r;
}
__device__ __forceinline__ float blk_red_prod(float v, float* sb, int t) {
#pragma unroll
    for (int o = 16; o; o >>= 1) v *= __shfl_xor_sync(0xffffffffu, v, o);
    __syncthreads();
    if ((t & 31) == 0) sb[t >> 5] = v;
    __syncthreads();
    float r = 1.f;
#pragma unroll
    for (int i = 0; i < 16; i++) r *= sb[i];
    return r;
}
// packed float4 reductions (512 threads)
__device__ __forceinline__ float4 blk_red_max4(float4 v, float4* sb, int t) {
#pragma unroll
    for (int o = 16; o; o >>= 1) {
        v.x = fmaxf(v.x, __shfl_xor_sync(0xffffffffu, v.x, o));
        v.y = fmaxf(v.y, __shfl_xor_sync(0xffffffffu, v.y, o));
        v.z = fmaxf(v.z, __shfl_xor_sync(0xffffffffu, v.z, o));
        v.w = fmaxf(v.w, __shfl_xor_sync(0xffffffffu, v.w, o));
    }
    __syncthreads();
    if ((t & 31) == 0) sb[t >> 5] = v;
    __syncthreads();
    float4 r = sb[0];
#pragma unroll
    for (int i = 1; i < 16; i++) {
        float4 s = sb[i];
        r.x = fmaxf(r.x, s.x); r.y = fmaxf(r.y, s.y);
        r.z = fmaxf(r.z, s.z); r.w = fmaxf(r.w, s.w);
    }
    return r;
}
__device__ __forceinline__ float4 blk_red_sum4(float4 v, float4* sb, int t) {
#pragma unroll
    for (int o = 16; o; o >>= 1) {
        v.x += __shfl_xor_sync(0xffffffffu, v.x, o);
        v.y += __shfl_xor_sync(0xffffffffu, v.y, o);
        v.z += __shfl_xor_sync(0xffffffffu, v.z, o);
        v.w += __shfl_xor_sync(0xffffffffu, v.w, o);
    }
    __syncthreads();
    if ((t & 31) == 0) sb[t >> 5] = v;
    __syncthreads();
    float4 r = sb[0];
#pragma unroll
    for (int i = 1; i < 16; i++) {
        float4 s = sb[i];
        r.x += s.x; r.y += s.y; r.z += s.z; r.w += s.w;
    }
    return r;
}

// ---------------------------------------------------------------------------
// Register-tiled GEMM body (32x32 tile, 128 threads, 2x4 micro),
// single-sync double-buffered. Row mapping: global_row = row_mul*(m0+m)+row_off
// (lets the same body compute even-row / odd-row halves).
// ---------------------------------------------------------------------------
__device__ __forceinline__ void gemm_body(const float* __restrict__ A,
                                          const float* __restrict__ B,
                                          const float* __restrict__ bias,
                                          float* __restrict__ C,
                                          int N, int K,
                                          int row_mul, int row_off,
                                          int m0, int n0) {
    __shared__ __align__(16) float Ast[2][32][34];
    __shared__ __align__(16) float Bs[2][32][32];
    int t = threadIdx.x;            // 128 active threads
    if (n0 >= N) return;
    int tx = t & 7;
    int ty = t >> 3;
    float acc[2][4] = {{0.f,0.f,0.f,0.f},{0.f,0.f,0.f,0.f}};
    int nkt = (K + 31) / 32;

    // preload tile 0 straight into smem buffer 0
#pragma unroll
    for (int i = 0; i < 8; i++) {
        int e = t + i * 128;
        int k = e & 31, m = e >> 5;
        int grow = row_mul * (m0 + m) + row_off;
        Ast[0][k][m] = (k < K) ? A[grow * K + k] : 0.f;
    }
#pragma unroll
    for (int i = 0; i < 8; i++) {
        int e = t + i * 128;
        int c = e & 31, k = e >> 5;
        Bs[0][k][c] = (k < K && n0 + c < N) ? B[k * N + n0 + c] : 0.f;
    }
    __syncthreads();

    float ra[8], rb[8];
    for (int kt = 0; kt < nkt; kt++) {
        int cur = kt & 1;
        bool more = (kt + 1 < nkt);
        if (more) {
            int k0n = (kt + 1) * 32;
#pragma unroll
            for (int i = 0; i < 8; i++) {
                int e = t + i * 128;
                int k = e & 31, m = e >> 5;
                int grow = row_mul * (m0 + m) + row_off;
                ra[i] = (k0n + k < K) ? A[grow * K + k0n + k] : 0.f;
            }
#pragma unroll
            for (int i = 0; i < 8; i++) {
                int e = t + i * 128;
                int c = e & 31, k = e >> 5;
                rb[i] = (k0n + k < K && n0 + c < N) ? B[(k0n + k) * N + n0 + c] : 0.f;
            }
        }
#pragma unroll
        for (int kk = 0; kk < 32; kk++) {
            float2 a2 = *(const float2*)&Ast[cur][kk][ty * 2];
            float4 b4 = *(const float4*)&Bs[cur][kk][tx * 4];
            acc[0][0] += a2.x * b4.x; acc[0][1] += a2.x * b4.y;
            acc[0][2] += a2.x * b4.z; acc[0][3] += a2.x * b4.w;
            acc[1][0] += a2.y * b4.x; acc[1][1] += a2.y * b4.y;
            acc[1][2] += a2.y * b4.z; acc[1][3] += a2.y * b4.w;
        }
        if (more) {
            int nxt = cur ^ 1;
#pragma unroll
            for (int i = 0; i < 8; i++) {
                int e = t + i * 128;
                Ast[nxt][e & 31][e >> 5] = ra[i];
            }
#pragma unroll
            for (int i = 0; i < 8; i++) {
                int e = t + i * 128;
                Bs[nxt][e >> 5][e & 31] = rb[i];
            }
            __syncthreads();
        }
    }
#pragma unroll
    for (int i = 0; i < 2; i++) {
        int row = row_mul * (m0 + ty * 2 + i) + row_off;
#pragma unroll
        for (int j = 0; j < 4; j++) {
            int col = n0 + tx * 4 + j;
            if (col < N) {
                float v = acc[i][j];
                if (bias) v += bias[col];
                C[row * N + col] = v;
            }
        }
    }
}

__global__ void gemm_gru(const float* __restrict__ X, const float* __restrict__ H,
                         const float* __restrict__ gk, const float* __restrict__ grk,
                         const float* __restrict__ gb) {
    if (blockIdx.z == 0)
        gemm_body(X, gk, gb, g_mx, G3, IND, 1, 0, blockIdx.y * 32, blockIdx.x * 32);
    else
        gemm_body(H, grk, gb + G3, g_mh, G3, CD, 1, 0, blockIdx.y * 32, blockIdx.x * 32);
}

// write-half interface: rows 2b+1 only (64 rows). grid (15, 2), 128 threads.
__global__ void gemm_iface_w(const float* __restrict__ hc, const float* __restrict__ Wif) {
    gemm_body(hc, Wif, nullptr, g_iface, IFC, CD, 2, 1, blockIdx.y * 32, blockIdx.x * 32);
}

// ---------------------------------------------------------------------------
// GRU combine: c = z*h + (1-z)*gelu(xh + r*rh)
// ---------------------------------------------------------------------------
__global__ void gru_combine(const float* __restrict__ h, float* __restrict__ hc_out) {
    int idx = blockIdx.x * blockDim.x + threadIdx.x;
    if (idx >= 128 * CD) return;
    int row = idx / CD, j = idx % CD;
    const float* mx = g_mx + row * G3;
    const float* mh = g_mh + row * G3;
    float z = sigmoidf_(mx[j] + mh[j]);
    float r = sigmoidf_(mx[CD + j] + mh[CD + j]);
    float hin = mx[2 * CD + j] + r * mh[2 * CD + j];
    float hh = hin * normcdff(hin);   // exact gelu
    float hv = h[idx];
    hc_out[idx] = z * hv + (1.f - z) * hh;
}

// ---------------------------------------------------------------------------
// Fused memory update: grid (2, 64) x 512 threads.
// ---------------------------------------------------------------------------
__global__ void memupdate_kernel(const float* __restrict__ W_read,
                                 const float* __restrict__ W_write,
                                 const float* __restrict__ usage,
                                 const float* __restrict__ M,
                                 const float* __restrict__ Wp,
                                 float* __restrict__ usage_out,
                                 float* __restrict__ Ww_out,
                                 float* __restrict__ Wp_out) {
    __shared__ __align__(16) float us[NMEM];
    __shared__ float ps[NMEM];
    __shared__ float es[NMEM];
    __shared__ __align__(16) float ks[WD];
    __shared__ float sb[16];
    int b = blockIdx.y, h = blockIdx.x, t = threadIdx.x;   // 512 threads
    int tt = t & 255;
    int np = h * 256 + tt;
    const float* ifw = g_iface + (2 * b + 1) * IFC;

    // 1) issue long-latency loads immediately
    float4 mreg[16];
    {
        const float4* m4p = (const float4*)(M + (b * NMEM + t) * WD);
#pragma unroll
        for (int i = 0; i < 16; i++) mreg[i] = m4p[i];
    }
    float wpv = Wp[b * NMEM + np];     // prefetch precedence (used at tail)

    // 2) usage for global row t
    float4 wr4 = *(const float4*)(W_read + (b * NMEM + t) * RH);
    float ret = (1.f - sigmoidf_(ifw[453]) * wr4.x)
              * (1.f - sigmoidf_(ifw[454]) * wr4.y)
              * (1.f - sigmoidf_(ifw[455]) * wr4.z)
              * (1.f - sigmoidf_(ifw[456]) * wr4.w);
    float u = usage[b * NMEM + t], w = W_write[b * NMEM + t];
    float un = (u + w - u * w) * ret;
    us[t] = un;
    if ((t >> 8) == h) usage_out[b * NMEM + t] = un;
    if (t < WD) ks[t] = ifw[260 + t];

    // 3) interface scalars, per-thread (broadcast loads)
    float bw = 1.f + softplusf_(ifw[324]);
    float ag = sigmoidf_(ifw[457]);
    float wg = sigmoidf_(ifw[458]);

    // 4) memory-row norm from registers
    float nrm = 0.f;
#pragma unroll
    for (int i = 0; i < 16; i++) {
        float4 m4 = mreg[i];
        nrm += m4.x * m4.x + m4.y * m4.y + m4.z * m4.z + m4.w * m4.w;
    }
    __syncthreads();   // publish us, ks

    // 5) raw dot + key norm (redundant per-thread)
    float dot = 0.f, ksum = 0.f;
    {
        const float4* ks4 = (const float4*)ks;
#pragma unroll
        for (int i = 0; i < 16; i++) {
            float4 m4 = mreg[i];
            float4 k4 = ks4[i];
            dot  += m4.x * k4.x + m4.y * k4.y + m4.z * k4.z + m4.w * k4.w;
            ksum += k4.x * k4.x + k4.y * k4.y + k4.z * k4.z + k4.w * k4.w;
        }
    }
    float s = dot * (1.f / sqrtf(fmaxf(nrm, 1e-12f)))
                  * (1.f / sqrtf(fmaxf(ksum, 1e-12f))) * bw;

    // 6) alloc half-product for row np (strict-less; 4 ILP chains)
    float unp = us[np];
    {
        float p0 = 1.f, p1 = 1.f, p2 = 1.f, p3 = 1.f;
        const float4* us4 = (const float4*)us;
        int i0 = (t >> 8) * 64;
#pragma unroll 4
        for (int i = i0; i < i0 + 64; i++) {
            float4 u4 = us4[i];
            p0 *= (u4.x < unp) ? u4.x : 1.f;
            p1 *= (u4.y < unp) ? u4.y : 1.f;
            p2 *= (u4.z < unp) ? u4.z : 1.f;
            p3 *= (u4.w < unp) ? u4.w : 1.f;
        }
        ps[t] = (p0 * p1) * (p2 * p3);
    }

    // 7) reductions
    float P = blk_red_prod(un, sb, t);
    float mxv = blk_red_max(s, sb, t);
    float e = expf(s - mxv);
    es[t] = e;
    float ssum = blk_red_sum(e, sb, t);

    if (t < 256) {
        float wl = es[np] / ssum;
        float walloc = (1.f - unp) * ps[t] * ps[t + 256];
        float ww = wg * (ag * walloc + (1.f - ag) * wl);
        Ww_out[b * NMEM + np] = ww;
        float wsum = wg * (ag * (1.f - P) + (1.f - ag));
        Wp_out[b * NMEM + np] = (1.f - wsum) * wpv + ww;
    }
}

// ---------------------------------------------------------------------------
// Link update + fused fwd/bwd partials (x 0..63) + M_n chunks (x 64..67)
// + read-half iface GEMM (x == 68, y < 30). grid (69, 64), block 256.
// ---------------------------------------------------------------------------
__global__ void link_kernel(const float* __restrict__ L, const float* __restrict__ Ww,
                            const float* __restrict__ Wp, const float* __restrict__ Wr,
                            const float* __restrict__ M, float* __restrict__ Mn_out,
                            float* __restrict__ Ln_out,
                            const float* __restrict__ hc, const float* __restrict__ Wif) {
    __shared__ __align__(16) float Ln_s[64][68];
    __shared__ float Wwi[64], Wwj[64], Wpj[64];
    __shared__ float Wri[64][4], Wrj[64][4];
    int b = blockIdx.y;
    int t = threadIdx.x;

    if (blockIdx.x == 68) {
        // ---- read-half iface GEMM: rows 2b, 30 tile-blocks ----
        if (blockIdx.y >= 30) return;
        if (t >= 128) return;          // exited threads skip inner barriers (ok)
        int ct = blockIdx.y % 15, rt = blockIdx.y / 15;
        gemm_body(hc, Wif, nullptr, g_iface, IFC, CD, 2, 0, rt * 32, ct * 32);
        return;
    }

    if (blockIdx.x >= 64) {
        // ---- M_n chunk: 128 rows of this batch ----
        int n0 = (blockIdx.x - 64) * 128;
        const float* ifw = g_iface + (2 * b + 1) * IFC;
        // prefetch M rows before smem setup
        const float4* M4 = (const float4*)(M + (b * NMEM + n0) * WD);
        float4 mreg[8];
#pragma unroll
        for (int i = 0; i < 8; i++) mreg[i] = M4[t + i * 256];
        float* es_ = &Ln_s[0][0];          // 64
        float* vs_ = &Ln_s[1][0];          // 64
        float* wws_ = &Ln_s[2][0];         // 128
        if (t < WD) { es_[t] = sigmoidf_(ifw[325 + t]); vs_[t] = ifw[389 + t]; }
        if (t >= 64 && t < 192) wws_[t - 64] = Ww[b * NMEM + n0 + t - 64];
        __syncthreads();
        float4* Mn4 = (float4*)(Mn_out + (b * NMEM + n0) * WD);
#pragma unroll
        for (int i = 0; i < 8; i++) {
            int idx4 = t + i * 256;
            int n = idx4 >> 4, w4 = (idx4 & 15) * 4;
            float wwn = wws_[n];
            float4 m4 = mreg[i];
            float4 o;
            o.x = m4.x * (1.f - wwn * es_[w4 + 0]) + wwn * vs_[w4 + 0];
            o.y = m4.y * (1.f - wwn * es_[w4 + 1]) + wwn * vs_[w4 + 1];
            o.z = m4.z * (1.f - wwn * es_[w4 + 2]) + wwn * vs_[w4 + 2];
            o.w = m4.w * (1.f - wwn * es_[w4 + 3]) + wwn * vs_[w4 + 3];
            Mn4[idx4] = o;
        }
        return;
    }

    int it = blockIdx.x >> 3, jt = blockIdx.x & 7;
    int i0 = it * 64, j0 = jt * 64;
    if (t < 64) {
        Wwi[t] = Ww[b * NMEM + i0 + t];
        Wwj[t] = Ww[b * NMEM + j0 + t];
        Wpj[t] = Wp[b * NMEM + j0 + t];
    }
    {
        int n = t >> 2, r = t & 3;
        Wri[n][r] = Wr[(b * NMEM + i0 + n) * RH + r];
        Wrj[n][r] = Wr[(b * NMEM + j0 + n) * RH + r];
    }
    __syncthreads();
#pragma unroll
    for (int k = 0; k < 4; k++) {
        int e4 = t + k * 256;
        int il = e4 >> 4, j4 = (e4 & 15) * 4;
        long gidx = ((long)(b * NMEM + i0 + il)) * NMEM + j0 + j4;
        float4 l4 = *(const float4*)(L + gidx);
        float wwi = Wwi[il];
        float4 ln;
        ln.x = (1.f - wwi - Wwj[j4 + 0]) * l4.x + wwi * Wpj[j4 + 0];
        ln.y = (1.f - wwi - Wwj[j4 + 1]) * l4.y + wwi * Wpj[j4 + 1];
        ln.z = (1.f - wwi - Wwj[j4 + 2]) * l4.z + wwi * Wpj[j4 + 2];
        ln.w = (1.f - wwi - Wwj[j4 + 3]) * l4.w + wwi * Wpj[j4 + 3];
        if (it == jt) {
            if (il == j4 + 0) ln.x = 0.f;
            if (il == j4 + 1) ln.y = 0.f;
            if (il == j4 + 2) ln.z = 0.f;
            if (il == j4 + 3) ln.w = 0.f;
        }
        *(float4*)&Ln_s[il][j4] = ln;
        *(float4*)(Ln_out + gidx) = ln;
    }
    __syncthreads();
    {
        int il = t >> 2, r = t & 3;
        float accF = 0.f, accB = 0.f;
#pragma unroll
        for (int c = 0; c < 64; c++) {
            accF += Ln_s[il][c] * Wrj[c][r];
            accB += Ln_s[c][il] * Wri[c][r];
        }
        g_fwdpart[((b * 8 + jt) * NMEM + i0 + il) * RH + r] = accF;
        g_bwdpart[((b * 8 + it) * NMEM + j0 + il) * RH + r] = accB;
    }
}

// ---------------------------------------------------------------------------
// Fused: partial reduce + read content lookup + mode mix -> Wr_n
//        + read vectors + output projection. 64 blocks x 512 threads.
// ---------------------------------------------------------------------------
__global__ void read_fused_kernel(const float* __restrict__ Mn,
                                  const float* __restrict__ Wro,
                                  float* __restrict__ Wr_out,
                                  float* __restrict__ y_out) {
    __shared__ __align__(16) float fwd_s[NMEM * RH];
    __shared__ __align__(16) float bwd_s[NMEM * RH];
    __shared__ float Wrs[NMEM][RH];
    __shared__ __align__(16) float nk[RH][WD];   // RAW keys
    __shared__ float br[RH];
    __shared__ float m0s[RH], m1s[RH], m2s[RH];
    __shared__ __align__(16) float4 sb4[16];
    __shared__ __align__(16) float4 partf[512];  // 8KB
    __shared__ __align__(16) float rv[256];
    __shared__ float party[512];
    int b = blockIdx.x, t = threadIdx.x;
    const float* ifr = g_iface + (2 * b) * IFC;

    // prefetch this thread's Mn row (used for content lookup)
    float4 mreg[16];
    {
        const float4* m4p = (const float4*)(Mn + (b * NMEM + t) * WD);
#pragma unroll
        for (int i = 0; i < 16; i++) mreg[i] = m4p[i];
    }

    // reduce 8 fwd/bwd partial tiles (float4)
    {
        float4 f4 = make_float4(0.f, 0.f, 0.f, 0.f);
        float4 b4 = make_float4(0.f, 0.f, 0.f, 0.f);
#pragma unroll
        for (int c = 0; c < 8; c++) {
            const float4* fp = (const float4*)(g_fwdpart + (b * 8 + c) * (NMEM * RH)) + t;
            const float4* bp = (const float4*)(g_bwdpart + (b * 8 + c) * (NMEM * RH)) + t;
            float4 fv = *fp, bv = *bp;
            f4.x += fv.x; f4.y += fv.y; f4.z += fv.z; f4.w += fv.w;
            b4.x += bv.x; b4.y += bv.y; b4.z += bv.z; b4.w += bv.w;
        }
        ((float4*)fwd_s)[t] = f4;
        ((float4*)bwd_s)[t] = b4;
    }
    if (t < RH * WD) {
        int r = t >> 6, w = t & 63;
        nk[r][w] = ifr[r * WD + w];   // raw, no normalization
    }
    if (t >= 256 && t < 256 + RH) {
        int r = t - 256;
        br[r] = 1.f + softplusf_(ifr[256 + r]);
        float a = ifr[459 + r], bb = ifr[463 + r], c = ifr[467 + r];
        float mx = fmaxf(a, fmaxf(bb, c));
        float ea = expf(a - mx), eb = expf(bb - mx), ec = expf(c - mx);
        float s = ea + eb + ec;
        m0s[r] = ea / s; m1s[r] = eb / s; m2s[r] = ec / s;
    }
    __syncthreads();

    // content lookup: raw dots + redundant per-thread key norms
    float d[RH] = {0.f, 0.f, 0.f, 0.f};
    float kn[RH] = {0.f, 0.f, 0.f, 0.f};
    float nrm = 0.f;
#pragma unroll
    for (int i = 0; i < 16; i++) {
        float4 m4 = mreg[i];
        nrm += m4.x * m4.x + m4.y * m4.y + m4.z * m4.z + m4.w * m4.w;
#pragma unroll
        for (int r = 0; r < RH; r++) {
            float4 k4 = ((const float4*)nk[r])[i];
            d[r]  += m4.x * k4.x + m4.y * k4.y + m4.z * k4.z + m4.w * k4.w;
            kn[r] += k4.x * k4.x + k4.y * k4.y + k4.z * k4.z + k4.w * k4.w;
        }
    }
    float rn = 1.f / sqrtf(fmaxf(nrm, 1e-12f));
    float4 sp = make_float4(
        d[0] * rn * (1.f / sqrtf(fmaxf(kn[0], 1e-12f))) * br[0],
        d[1] * rn * (1.f / sqrtf(fmaxf(kn[1], 1e-12f))) * br[1],
        d[2] * rn * (1.f / sqrtf(fmaxf(kn[2], 1e-12f))) * br[2],
        d[3] * rn * (1.f / sqrtf(fmaxf(kn[3], 1e-12f))) * br[3]);
    float4 mx4 = blk_red_max4(sp, sb4, t);
    float4 e4 = make_float4(expf(sp.x - mx4.x), expf(sp.y - mx4.y),
                            expf(sp.z - mx4.z), expf(sp.w - mx4.w));
    float4 sum4 = blk_red_sum4(e4, sb4, t);
    float wl[RH] = {e4.x / sum4.x, e4.y / sum4.y, e4.z / sum4.z, e4.w / sum4.w};

#pragma unroll
    for (int r = 0; r < RH; r++) {
        float v = m0s[r] * bwd_s[t * RH + r] + m1s[r] * wl[r] + m2s[r] * fwd_s[t * RH + r];
        Wr_out[(b * NMEM + t) * RH + r] = v;
        Wrs[t][r] = v;
    }
    __syncthreads();

    // read vectors (float4): thread = (slice=t>>6, r=(t>>4)&3, w4=t&15)
    {
        int slice = t >> 6, r = (t >> 4) & 3, w4 = t & 15;
        int n0 = slice * 64;
        float4 acc = make_float4(0.f, 0.f, 0.f, 0.f);
        const float4* Mn4 = (const float4*)(Mn + (b * NMEM + n0) * WD);
#pragma unroll 8
        for (int n = 0; n < 64; n++) {
            float4 m4 = Mn4[n * 16 + w4];
            float wr = Wrs[n0 + n][r];
            acc.x += m4.x * wr; acc.y += m4.y * wr;
            acc.z += m4.z * wr; acc.w += m4.w * wr;
        }
        partf[t] = acc;
    }
    __syncthreads();
    if (t < 64) {   // reduce 8 slices -> rv[r*64 + w]
        int r = t >> 4, w4 = t & 15;
        float4 s = make_float4(0.f, 0.f, 0.f, 0.f);
#pragma unroll
        for (int sl = 0; sl < 8; sl++) {
            float4 p = partf[sl * 64 + t];
            s.x += p.x; s.y += p.y; s.z += p.z; s.w += p.w;
        }
        *(float4*)&rv[r * 64 + w4 * 4] = s;
    }
    __syncthreads();
    // y = rv @ W_read_out ; all 512 threads (k-split)
    {
        int half = t >> 8, tt = t & 255;
        int k0 = half * 128;
        float ya = 0.f;
#pragma unroll 8
        for (int k = 0; k < 128; k++) ya += rv[k0 + k] * Wro[(k0 + k) * OUTD + tt];
        party[t] = ya;
    }
    __syncthreads();
    if (t < 256) y_out[b * OUTD + t] = party[t] + party[256 + t];
}

// ---------------------------------------------------------------------------
extern "C" void kernel_launch(void* const* d_in, const int* in_sizes, int n_in,
                              void* d_out, int out_size) {
    const float* inputs   = (const float*)d_in[0];
    const float* M        = (const float*)d_in[1];
    const float* usage    = (const float*)d_in[2];
    const float* L        = (const float*)d_in[3];
    const float* Wp       = (const float*)d_in[4];
    const float* W_read   = (const float*)d_in[5];
    const float* W_write  = (const float*)d_in[6];
    const float* h_ctrl   = (const float*)d_in[7];
    const float* W_iface  = (const float*)d_in[8];
    const float* W_rdout  = (const float*)d_in[9];
    const float* gru_k    = (const float*)d_in[10];
    const float* gru_rk   = (const float*)d_in[11];
    const float* gru_b    = (const float*)d_in[12];

    float* out = (float*)d_out;
    float* o_y    = out + OFF_Y;
    float* o_mn   = out + OFF_MN;
    float* o_use  = out + OFF_USAGE;
    float* o_ln   = out + OFF_LN;
    float* o_wp   = out + OFF_WP;
    float* o_wr   = out + OFF_WR;
    float* o_ww   = out + OFF_WW;
    float* o_hc   = out + OFF_HC;

    // 1) GRU mats mx & mh in one launch (double-buffered 32x32 tiles)
    gemm_gru<<<dim3((G3 + 31) / 32, 4, 2), 128>>>(inputs, h_ctrl, gru_k, gru_rk, gru_b);
    // 2) combine -> hc
    gru_combine<<<(128 * CD + 255) / 256, 256>>>(h_ctrl, o_hc);
    // 3) interface WRITE-half only (rows 2b+1) — critical path
    gemm_iface_w<<<dim3(15, 2), 128>>>(o_hc, W_iface);
    // 4) fused usage + alloc + write lookup + Ww + Wp
    memupdate_kernel<<<dim3(2, BSZ), 512>>>(W_read, W_write, usage, M, Wp,
                                            o_use, o_ww, o_wp);
    // 5) link update + fwd/bwd partials + M_n chunks + iface READ-half (x==68)
    link_kernel<<<dim3(69, BSZ), 256>>>(L, o_ww, Wp, W_read, M, o_mn, o_ln,
                                        o_hc, W_iface);
    // 6) fused reduce + read lookup + Wr + read vectors + y
    read_fused_kernel<<<BSZ, NMEM>>>(o_mn, W_rdout, o_wr, o_y);
}

// round 15
// speedup vs baseline: 1.0926x; 1.0926x over previous
#include <cuda_runtime.h>
#include <math.h>

// Problem dims
#define BSZ   64
#define NMEM  512
#define WD    64
#define RH    4
#define OUTD  256
#define IND   256
#define IFC   471     // interface size
#define CD    727     // controller dim
#define G3    2181    // 3*CD

// Output layout offsets (concatenated flattened tuple, f32)
#define OFF_Y      0
#define OFF_MN     16384
#define OFF_USAGE  2113536
#define OFF_LN     2146304
#define OFF_WP     18923520
#define OFF_WR     18956288
#define OFF_WW     19087360
#define OFF_HC     19120128

// Scratch (no cudaMalloc allowed)
__device__ float g_mx[128 * G3];
__device__ float g_mh[128 * G3];
__device__ float g_iface[128 * IFC];
__device__ __align__(16) float g_fwdpart[BSZ * 8 * NMEM * RH];
__device__ __align__(16) float g_bwdpart[BSZ * 8 * NMEM * RH];

__device__ __forceinline__ float sigmoidf_(float x) { return 1.f / (1.f + expf(-x)); }
__device__ __forceinline__ float softplusf_(float x) { return fmaxf(x, 0.f) + log1pf(expf(-fabsf(x))); }

// Block reductions for 512 threads (16 warps)
__device__ __forceinline__ float blk_red_max(float v, float* sb, int t) {
#pragma unroll
    for (int o = 16; o; o >>= 1) v = fmaxf(v, __shfl_xor_sync(0xffffffffu, v, o));
    __syncthreads();
    if ((t & 31) == 0) sb[t >> 5] = v;
    __syncthreads();
    float r = sb[0];
#pragma unroll
    for (int i = 1; i < 16; i++) r = fmaxf(r, sb[i]);
    return r;
}
__device__ __forceinline__ float blk_red_sum(float v, float* sb, int t) {
#pragma unroll
    for (int o = 16; o; o >>= 1) v += __shfl_xor_sync(0xffffffffu, v, o);
    __syncthreads();
    if ((t & 31) == 0) sb[t >> 5] = v;
    __syncthreads();
    float r = 0.f;
#pragma unroll
    for (int i = 0; i < 16; i++) r += sb[i];
    return r;
}
// packed: x-component product-reduce, y-component max-reduce (one pass)
__device__ __forceinline__ float2 blk_red_prodmax(float2 v, float2* sb, int t) {
#pragma unroll
    for (int o = 16; o; o >>= 1) {
        v.x *= __shfl_xor_sync(0xffffffffu, v.x, o);
        v.y = fmaxf(v.y, __shfl_xor_sync(0xffffffffu, v.y, o));
    }
    __syncthreads();
    if ((t & 31) == 0) sb[t >> 5] = v;
    __syncthreads();
    float2 r = sb[0];
#pragma unroll
    for (int i = 1; i < 16; i++) {
        float2 s = sb[i];
        r.x *= s.x;
        r.y = fmaxf(r.y, s.y);
    }
    return r;
}
// packed float4 reductions (512 threads)
__device__ __forceinline__ float4 blk_red_max4(float4 v, float4* sb, int t) {
#pragma unroll
    for (int o = 16; o; o >>= 1) {
        v.x = fmaxf(v.x, __shfl_xor_sync(0xffffffffu, v.x, o));
        v.y = fmaxf(v.y, __shfl_xor_sync(0xffffffffu, v.y, o));
        v.z = fmaxf(v.z, __shfl_xor_sync(0xffffffffu, v.z, o));
        v.w = fmaxf(v.w, __shfl_xor_sync(0xffffffffu, v.w, o));
    }
    __syncthreads();
    if ((t & 31) == 0) sb[t >> 5] = v;
    __syncthreads();
    float4 r = sb[0];
#pragma unroll
    for (int i = 1; i < 16; i++) {
        float4 s = sb[i];
        r.x = fmaxf(r.x, s.x); r.y = fmaxf(r.y, s.y);
        r.z = fmaxf(r.z, s.z); r.w = fmaxf(r.w, s.w);
    }
    return r;
}
__device__ __forceinline__ float4 blk_red_sum4(float4 v, float4* sb, int t) {
#pragma unroll
    for (int o = 16; o; o >>= 1) {
        v.x += __shfl_xor_sync(0xffffffffu, v.x, o);
        v.y += __shfl_xor_sync(0xffffffffu, v.y, o);
        v.z += __shfl_xor_sync(0xffffffffu, v.z, o);
        v.w += __shfl_xor_sync(0xffffffffu, v.w, o);
    }
    __syncthreads();
    if ((t & 31) == 0) sb[t >> 5] = v;
    __syncthreads();
    float4 r = sb[0];
#pragma unroll
    for (int i = 1; i < 16; i++) {
        float4 s = sb[i];
        r.x += s.x; r.y += s.y; r.z += s.z; r.w += s.w;
    }
    return r;
}

// ---------------------------------------------------------------------------
// Register-tiled GEMM body (32x32 tile, 128 threads, 2x4 micro),
// single-sync double-buffered (Round-13 winner).
// ---------------------------------------------------------------------------
__device__ __forceinline__ void gemm_body(const float* __restrict__ A,
                                          const float* __restrict__ B,
                                          const float* __restrict__ bias,
                                          float* __restrict__ C,
                                          int N, int K) {
    __shared__ __align__(16) float Ast[2][32][34];
    __shared__ __align__(16) float Bs[2][32][32];
    int t = threadIdx.x;            // 128 threads
    int m0 = blockIdx.y * 32;
    int n0 = blockIdx.x * 32;
    if (n0 >= N) return;
    int tx = t & 7;
    int ty = t >> 3;
    float acc[2][4] = {{0.f,0.f,0.f,0.f},{0.f,0.f,0.f,0.f}};
    int nkt = (K + 31) / 32;

    // preload tile 0 straight into smem buffer 0
#pragma unroll
    for (int i = 0; i < 8; i++) {
        int e = t + i * 128;
        int k = e & 31, m = e >> 5;
        Ast[0][k][m] = (k < K) ? A[(m0 + m) * K + k] : 0.f;
    }
#pragma unroll
    for (int i = 0; i < 8; i++) {
        int e = t + i * 128;
        int c = e & 31, k = e >> 5;
        Bs[0][k][c] = (k < K && n0 + c < N) ? B[k * N + n0 + c] : 0.f;
    }
    __syncthreads();

    float ra[8], rb[8];
    for (int kt = 0; kt < nkt; kt++) {
        int cur = kt & 1;
        bool more = (kt + 1 < nkt);
        if (more) {
            int k0n = (kt + 1) * 32;
#pragma unroll
            for (int i = 0; i < 8; i++) {
                int e = t + i * 128;
                int k = e & 31, m = e >> 5;
                ra[i] = (k0n + k < K) ? A[(m0 + m) * K + k0n + k] : 0.f;
            }
#pragma unroll
            for (int i = 0; i < 8; i++) {
                int e = t + i * 128;
                int c = e & 31, k = e >> 5;
                rb[i] = (k0n + k < K && n0 + c < N) ? B[(k0n + k) * N + n0 + c] : 0.f;
            }
        }
#pragma unroll
        for (int kk = 0; kk < 32; kk++) {
            float2 a2 = *(const float2*)&Ast[cur][kk][ty * 2];
            float4 b4 = *(const float4*)&Bs[cur][kk][tx * 4];
            acc[0][0] += a2.x * b4.x; acc[0][1] += a2.x * b4.y;
            acc[0][2] += a2.x * b4.z; acc[0][3] += a2.x * b4.w;
            acc[1][0] += a2.y * b4.x; acc[1][1] += a2.y * b4.y;
            acc[1][2] += a2.y * b4.z; acc[1][3] += a2.y * b4.w;
        }
        if (more) {
            int nxt = cur ^ 1;
#pragma unroll
            for (int i = 0; i < 8; i++) {
                int e = t + i * 128;
                Ast[nxt][e & 31][e >> 5] = ra[i];
            }
#pragma unroll
            for (int i = 0; i < 8; i++) {
                int e = t + i * 128;
                Bs[nxt][e >> 5][e & 31] = rb[i];
            }
            __syncthreads();
        }
    }
#pragma unroll
    for (int i = 0; i < 2; i++) {
        int row = m0 + ty * 2 + i;
#pragma unroll
        for (int j = 0; j < 4; j++) {
            int col = n0 + tx * 4 + j;
            if (col < N) {
                float v = acc[i][j];
                if (bias) v += bias[col];
                C[row * N + col] = v;
            }
        }
    }
}

__global__ void gemm_gru(const float* __restrict__ X, const float* __restrict__ H,
                         const float* __restrict__ gk, const float* __restrict__ grk,
                         const float* __restrict__ gb) {
    if (blockIdx.z == 0) gemm_body(X, gk, gb, g_mx, G3, IND);
    else                 gemm_body(H, grk, gb + G3, g_mh, G3, CD);
}

__global__ void gemm_iface(const float* __restrict__ hc, const float* __restrict__ Wif) {
    gemm_body(hc, Wif, nullptr, g_iface, IFC, CD);
}

// ---------------------------------------------------------------------------
// GRU combine: c = z*h + (1-z)*gelu(xh + r*rh)
// ---------------------------------------------------------------------------
__global__ void gru_combine(const float* __restrict__ h, float* __restrict__ hc_out) {
    int idx = blockIdx.x * blockDim.x + threadIdx.x;
    if (idx >= 128 * CD) return;
    int row = idx / CD, j = idx % CD;
    const float* mx = g_mx + row * G3;
    const float* mh = g_mh + row * G3;
    float z = sigmoidf_(mx[j] + mh[j]);
    float r = sigmoidf_(mx[CD + j] + mh[CD + j]);
    float hin = mx[2 * CD + j] + r * mh[2 * CD + j];
    float hh = hin * normcdff(hin);   // exact gelu
    float hv = h[idx];
    hc_out[idx] = z * hv + (1.f - z) * hh;
}

// ---------------------------------------------------------------------------
// Fused memory update: grid (2, 64) x 512 threads.
// Prod+max merged into one packed reduction; Wp prefetched at top.
// ---------------------------------------------------------------------------
__global__ void memupdate_kernel(const float* __restrict__ W_read,
                                 const float* __restrict__ W_write,
                                 const float* __restrict__ usage,
                                 const float* __restrict__ M,
                                 const float* __restrict__ Wp,
                                 float* __restrict__ usage_out,
                                 float* __restrict__ Ww_out,
                                 float* __restrict__ Wp_out) {
    __shared__ __align__(16) float us[NMEM];
    __shared__ float ps[NMEM];
    __shared__ float es[NMEM];
    __shared__ __align__(16) float ks[WD];
    __shared__ __align__(16) float2 sb2[16];
    __shared__ float sb[16];
    int b = blockIdx.y, h = blockIdx.x, t = threadIdx.x;   // 512 threads
    int tt = t & 255;
    int np = h * 256 + tt;
    const float* ifw = g_iface + (2 * b + 1) * IFC;

    // 1) issue long-latency loads immediately
    float4 mreg[16];
    {
        const float4* m4p = (const float4*)(M + (b * NMEM + t) * WD);
#pragma unroll
        for (int i = 0; i < 16; i++) mreg[i] = m4p[i];
    }
    float wpv = Wp[b * NMEM + np];     // prefetch precedence

    // 2) usage for global row t
    float4 wr4 = *(const float4*)(W_read + (b * NMEM + t) * RH);
    float ret = (1.f - sigmoidf_(ifw[453]) * wr4.x)
              * (1.f - sigmoidf_(ifw[454]) * wr4.y)
              * (1.f - sigmoidf_(ifw[455]) * wr4.z)
              * (1.f - sigmoidf_(ifw[456]) * wr4.w);
    float u = usage[b * NMEM + t], w = W_write[b * NMEM + t];
    float un = (u + w - u * w) * ret;
    us[t] = un;
    if ((t >> 8) == h) usage_out[b * NMEM + t] = un;
    if (t < WD) ks[t] = ifw[260 + t];

    // 3) interface scalars, per-thread (broadcast loads)
    float bw = 1.f + softplusf_(ifw[324]);
    float ag = sigmoidf_(ifw[457]);
    float wg = sigmoidf_(ifw[458]);

    // 4) memory-row norm from registers
    float nrm = 0.f;
#pragma unroll
    for (int i = 0; i < 16; i++) {
        float4 m4 = mreg[i];
        nrm += m4.x * m4.x + m4.y * m4.y + m4.z * m4.z + m4.w * m4.w;
    }
    __syncthreads();   // publish us, ks

    // 5) raw dot + key norm (redundant per-thread)
    float dot = 0.f, ksum = 0.f;
    {
        const float4* ks4 = (const float4*)ks;
#pragma unroll
        for (int i = 0; i < 16; i++) {
            float4 m4 = mreg[i];
            float4 k4 = ks4[i];
            dot  += m4.x * k4.x + m4.y * k4.y + m4.z * k4.z + m4.w * k4.w;
            ksum += k4.x * k4.x + k4.y * k4.y + k4.z * k4.z + k4.w * k4.w;
        }
    }
    float s = dot * (1.f / sqrtf(fmaxf(nrm, 1e-12f)))
                  * (1.f / sqrtf(fmaxf(ksum, 1e-12f))) * bw;

    // 6) alloc half-product for row np (strict-less; 4 ILP chains)
    float unp = us[np];
    {
        float p0 = 1.f, p1 = 1.f, p2 = 1.f, p3 = 1.f;
        const float4* us4 = (const float4*)us;
        int i0 = (t >> 8) * 64;
#pragma unroll 4
        for (int i = i0; i < i0 + 64; i++) {
            float4 u4 = us4[i];
            p0 *= (u4.x < unp) ? u4.x : 1.f;
            p1 *= (u4.y < unp) ? u4.y : 1.f;
            p2 *= (u4.z < unp) ? u4.z : 1.f;
            p3 *= (u4.w < unp) ? u4.w : 1.f;
        }
        ps[t] = (p0 * p1) * (p2 * p3);
    }

    // 7) reductions: prod+max in one pass, then sum
    float2 pm = blk_red_prodmax(make_float2(un, s), sb2, t);
    float P = pm.x;
    float e = expf(s - pm.y);
    es[t] = e;
    float ssum = blk_red_sum(e, sb, t);   // barriers publish ps, es

    if (t < 256) {
        float wl = es[np] / ssum;
        float walloc = (1.f - unp) * ps[t] * ps[t + 256];
        float ww = wg * (ag * walloc + (1.f - ag) * wl);
        Ww_out[b * NMEM + np] = ww;
        float wsum = wg * (ag * (1.f - P) + (1.f - ag));
        Wp_out[b * NMEM + np] = (1.f - wsum) * wpv + ww;
    }
}

// ---------------------------------------------------------------------------
// Link update + fused fwd/bwd partials (x 0..63) + M_n chunks (x 64..67).
// grid (68, 64), block 256
// ---------------------------------------------------------------------------
__global__ void link_kernel(const float* __restrict__ L, const float* __restrict__ Ww,
                            const float* __restrict__ Wp, const float* __restrict__ Wr,
                            const float* __restrict__ M, float* __restrict__ Mn_out,
                            float* __restrict__ Ln_out) {
    __shared__ __align__(16) float Ln_s[64][68];
    __shared__ float Wwi[64], Wwj[64], Wpj[64];
    __shared__ float Wri[64][4], Wrj[64][4];
    int b = blockIdx.y;
    int t = threadIdx.x;

    if (blockIdx.x >= 64) {
        // ---- M_n chunk: 128 rows of this batch; M prefetched first ----
        int n0 = (blockIdx.x - 64) * 128;
        const float* ifw = g_iface + (2 * b + 1) * IFC;
        const float4* M4 = (const float4*)(M + (b * NMEM + n0) * WD);
        float4 mreg[8];
#pragma unroll
        for (int i = 0; i < 8; i++) mreg[i] = M4[t + i * 256];
        float* es_ = &Ln_s[0][0];          // 64
        float* vs_ = &Ln_s[1][0];          // 64
        float* wws_ = &Ln_s[2][0];         // 128
        if (t < WD) { es_[t] = sigmoidf_(ifw[325 + t]); vs_[t] = ifw[389 + t]; }
        if (t >= 64 && t < 192) wws_[t - 64] = Ww[b * NMEM + n0 + t - 64];
        __syncthreads();
        float4* Mn4 = (float4*)(Mn_out + (b * NMEM + n0) * WD);
#pragma unroll
        for (int i = 0; i < 8; i++) {
            int idx4 = t + i * 256;
            int n = idx4 >> 4, w4 = (idx4 & 15) * 4;
            float wwn = wws_[n];
            float4 m4 = mreg[i];
            float4 o;
            o.x = m4.x * (1.f - wwn * es_[w4 + 0]) + wwn * vs_[w4 + 0];
            o.y = m4.y * (1.f - wwn * es_[w4 + 1]) + wwn * vs_[w4 + 1];
            o.z = m4.z * (1.f - wwn * es_[w4 + 2]) + wwn * vs_[w4 + 2];
            o.w = m4.w * (1.f - wwn * es_[w4 + 3]) + wwn * vs_[w4 + 3];
            Mn4[idx4] = o;
        }
        return;
    }

    int it = blockIdx.x >> 3, jt = blockIdx.x & 7;
    int i0 = it * 64, j0 = jt * 64;
    if (t < 64) {
        Wwi[t] = Ww[b * NMEM + i0 + t];
        Wwj[t] = Ww[b * NMEM + j0 + t];
        Wpj[t] = Wp[b * NMEM + j0 + t];
    }
    {
        int n = t >> 2, r = t & 3;
        Wri[n][r] = Wr[(b * NMEM + i0 + n) * RH + r];
        Wrj[n][r] = Wr[(b * NMEM + j0 + n) * RH + r];
    }
    __syncthreads();
#pragma unroll
    for (int k = 0; k < 4; k++) {
        int e4 = t + k * 256;
        int il = e4 >> 4, j4 = (e4 & 15) * 4;
        long gidx = ((long)(b * NMEM + i0 + il)) * NMEM + j0 + j4;
        float4 l4 = *(const float4*)(L + gidx);
        float wwi = Wwi[il];
        float4 ln;
        ln.x = (1.f - wwi - Wwj[j4 + 0]) * l4.x + wwi * Wpj[j4 + 0];
        ln.y = (1.f - wwi - Wwj[j4 + 1]) * l4.y + wwi * Wpj[j4 + 1];
        ln.z = (1.f - wwi - Wwj[j4 + 2]) * l4.z + wwi * Wpj[j4 + 2];
        ln.w = (1.f - wwi - Wwj[j4 + 3]) * l4.w + wwi * Wpj[j4 + 3];
        if (it == jt) {
            if (il == j4 + 0) ln.x = 0.f;
            if (il == j4 + 1) ln.y = 0.f;
            if (il == j4 + 2) ln.z = 0.f;
            if (il == j4 + 3) ln.w = 0.f;
        }
        *(float4*)&Ln_s[il][j4] = ln;
        *(float4*)(Ln_out + gidx) = ln;
    }
    __syncthreads();
    {
        int il = t >> 2, r = t & 3;
        float accF = 0.f, accB = 0.f;
#pragma unroll
        for (int c = 0; c < 64; c++) {
            accF += Ln_s[il][c] * Wrj[c][r];
            accB += Ln_s[c][il] * Wri[c][r];
        }
        g_fwdpart[((b * 8 + jt) * NMEM + i0 + il) * RH + r] = accF;
        g_bwdpart[((b * 8 + it) * NMEM + j0 + il) * RH + r] = accB;
    }
}

// ---------------------------------------------------------------------------
// Fused: partial reduce + read content lookup + mode mix -> Wr_n
//        + read vectors + output projection. 64 blocks x 512 threads.
// ---------------------------------------------------------------------------
__global__ void read_fused_kernel(const float* __restrict__ Mn,
                                  const float* __restrict__ Wro,
                                  float* __restrict__ Wr_out,
                                  float* __restrict__ y_out) {
    __shared__ __align__(16) float fwd_s[NMEM * RH];
    __shared__ __align__(16) float bwd_s[NMEM * RH];
    __shared__ float Wrs[NMEM][RH];
    __shared__ __align__(16) float nk[RH][WD];   // RAW keys
    __shared__ float br[RH];
    __shared__ float m0s[RH], m1s[RH], m2s[RH];
    __shared__ __align__(16) float4 sb4[16];
    __shared__ __align__(16) float4 partf[512];  // 8KB
    __shared__ __align__(16) float rv[256];
    __shared__ float party[512];
    int b = blockIdx.x, t = threadIdx.x;
    const float* ifr = g_iface + (2 * b) * IFC;

    // reduce 8 fwd/bwd partial tiles (float4)
    {
        float4 f4 = make_float4(0.f, 0.f, 0.f, 0.f);
        float4 b4 = make_float4(0.f, 0.f, 0.f, 0.f);
#pragma unroll
        for (int c = 0; c < 8; c++) {
            const float4* fp = (const float4*)(g_fwdpart + (b * 8 + c) * (NMEM * RH)) + t;
            const float4* bp = (const float4*)(g_bwdpart + (b * 8 + c) * (NMEM * RH)) + t;
            float4 fv = *fp, bv = *bp;
            f4.x += fv.x; f4.y += fv.y; f4.z += fv.z; f4.w += fv.w;
            b4.x += bv.x; b4.y += bv.y; b4.z += bv.z; b4.w += bv.w;
        }
        ((float4*)fwd_s)[t] = f4;
        ((float4*)bwd_s)[t] = b4;
    }
    if (t < RH * WD) {
        int r = t >> 6, w = t & 63;
        nk[r][w] = ifr[r * WD + w];   // raw, no normalization
    }
    if (t >= 256 && t < 256 + RH) {
        int r = t - 256;
        br[r] = 1.f + softplusf_(ifr[256 + r]);
        float a = ifr[459 + r], bb = ifr[463 + r], c = ifr[467 + r];
        float mx = fmaxf(a, fmaxf(bb, c));
        float ea = expf(a - mx), eb = expf(bb - mx), ec = expf(c - mx);
        float s = ea + eb + ec;
        m0s[r] = ea / s; m1s[r] = eb / s; m2s[r] = ec / s;
    }
    __syncthreads();

    // content lookup: raw dots + redundant per-thread key norms
    const float4* m4p = (const float4*)(Mn + (b * NMEM + t) * WD);
    float d[RH] = {0.f, 0.f, 0.f, 0.f};
    float kn[RH] = {0.f, 0.f, 0.f, 0.f};
    float nrm = 0.f;
#pragma unroll
    for (int i = 0; i < 16; i++) {
        float4 m4 = m4p[i];
        nrm += m4.x * m4.x + m4.y * m4.y + m4.z * m4.z + m4.w * m4.w;
#pragma unroll
        for (int r = 0; r < RH; r++) {
            float4 k4 = ((const float4*)nk[r])[i];
            d[r]  += m4.x * k4.x + m4.y * k4.y + m4.z * k4.z + m4.w * k4.w;
            kn[r] += k4.x * k4.x + k4.y * k4.y + k4.z * k4.z + k4.w * k4.w;
        }
    }
    float rn = 1.f / sqrtf(fmaxf(nrm, 1e-12f));
    float4 sp = make_float4(
        d[0] * rn * (1.f / sqrtf(fmaxf(kn[0], 1e-12f))) * br[0],
        d[1] * rn * (1.f / sqrtf(fmaxf(kn[1], 1e-12f))) * br[1],
        d[2] * rn * (1.f / sqrtf(fmaxf(kn[2], 1e-12f))) * br[2],
        d[3] * rn * (1.f / sqrtf(fmaxf(kn[3], 1e-12f))) * br[3]);
    float4 mx4 = blk_red_max4(sp, sb4, t);
    float4 e4 = make_float4(expf(sp.x - mx4.x), expf(sp.y - mx4.y),
                            expf(sp.z - mx4.z), expf(sp.w - mx4.w));
    float4 sum4 = blk_red_sum4(e4, sb4, t);
    float wl[RH] = {e4.x / sum4.x, e4.y / sum4.y, e4.z / sum4.z, e4.w / sum4.w};

#pragma unroll
    for (int r = 0; r < RH; r++) {
        float v = m0s[r] * bwd_s[t * RH + r] + m1s[r] * wl[r] + m2s[r] * fwd_s[t * RH + r];
        Wr_out[(b * NMEM + t) * RH + r] = v;
        Wrs[t][r] = v;
    }
    __syncthreads();

    // read vectors (float4): thread = (slice=t>>6, r=(t>>4)&3, w4=t&15)
    {
        int slice = t >> 6, r = (t >> 4) & 3, w4 = t & 15;
        int n0 = slice * 64;
        float4 acc = make_float4(0.f, 0.f, 0.f, 0.f);
        const float4* Mn4 = (const float4*)(Mn + (b * NMEM + n0) * WD);
#pragma unroll 8
        for (int n = 0; n < 64; n++) {
            float4 m4 = Mn4[n * 16 + w4];
            float wr = Wrs[n0 + n][r];
            acc.x += m4.x * wr; acc.y += m4.y * wr;
            acc.z += m4.z * wr; acc.w += m4.w * wr;
        }
        partf[t] = acc;
    }
    __syncthreads();
    if (t < 64) {   // reduce 8 slices -> rv[r*64 + w]
        int r = t >> 4, w4 = t & 15;
        float4 s = make_float4(0.f, 0.f, 0.f, 0.f);
#pragma unroll
        for (int sl = 0; sl < 8; sl++) {
            float4 p = partf[sl * 64 + t];
            s.x += p.x; s.y += p.y; s.z += p.z; s.w += p.w;
        }
        *(float4*)&rv[r * 64 + w4 * 4] = s;
    }
    __syncthreads();
    // y = rv @ W_read_out ; all 512 threads (k-split)
    {
        int half = t >> 8, tt = t & 255;
        int k0 = half * 128;
        float ya = 0.f;
#pragma unroll 8
        for (int k = 0; k < 128; k++) ya += rv[k0 + k] * Wro[(k0 + k) * OUTD + tt];
        party[t] = ya;
    }
    __syncthreads();
    if (t < 256) y_out[b * OUTD + t] = party[t] + party[256 + t];
}

// ---------------------------------------------------------------------------
extern "C" void kernel_launch(void* const* d_in, const int* in_sizes, int n_in,
                              void* d_out, int out_size) {
    const float* inputs   = (const float*)d_in[0];
    const float* M        = (const float*)d_in[1];
    const float* usage    = (const float*)d_in[2];
    const float* L        = (const float*)d_in[3];
    const float* Wp       = (const float*)d_in[4];
    const float* W_read   = (const float*)d_in[5];
    const float* W_write  = (const float*)d_in[6];
    const float* h_ctrl   = (const float*)d_in[7];
    const float* W_iface  = (const float*)d_in[8];
    const float* W_rdout  = (const float*)d_in[9];
    const float* gru_k    = (const float*)d_in[10];
    const float* gru_rk   = (const float*)d_in[11];
    const float* gru_b    = (const float*)d_in[12];

    float* out = (float*)d_out;
    float* o_y    = out + OFF_Y;
    float* o_mn   = out + OFF_MN;
    float* o_use  = out + OFF_USAGE;
    float* o_ln   = out + OFF_LN;
    float* o_wp   = out + OFF_WP;
    float* o_wr   = out + OFF_WR;
    float* o_ww   = out + OFF_WW;
    float* o_hc   = out + OFF_HC;

    // 1) GRU mats mx & mh in one launch (double-buffered 32x32 tiles)
    gemm_gru<<<dim3((G3 + 31) / 32, 4, 2), 128>>>(inputs, h_ctrl, gru_k, gru_rk, gru_b);
    // 2) combine -> hc
    gru_combine<<<(128 * CD + 255) / 256, 256>>>(h_ctrl, o_hc);
    // 3) interface = hc @ W_interface (full, single kernel — R13 config)
    gemm_iface<<<dim3((IFC + 31) / 32, 4), 128>>>(o_hc, W_iface);
    // 4) fused usage + alloc + write lookup + Ww + Wp
    memupdate_kernel<<<dim3(2, BSZ), 512>>>(W_read, W_write, usage, M, Wp,
                                            o_use, o_ww, o_wp);
    // 5) link update + fwd/bwd partials + M_n chunks
    link_kernel<<<dim3(68, BSZ), 256>>>(L, o_ww, Wp, W_read, M, o_mn, o_ln);
    // 6) fused reduce + read lookup + Wr + read vectors + y
    read_fused_kernel<<<BSZ, NMEM>>>(o_mn, W_rdout, o_wr, o_y);
}

// round 16
// speedup vs baseline: 1.1106x; 1.0165x over previous
#include <cuda_runtime.h>
#include <math.h>

// Problem dims
#define BSZ   64
#define NMEM  512
#define WD    64
#define RH    4
#define OUTD  256
#define IND   256
#define IFC   471     // interface size
#define CD    727     // controller dim
#define G3    2181    // 3*CD

// Output layout offsets (concatenated flattened tuple, f32)
#define OFF_Y      0
#define OFF_MN     16384
#define OFF_USAGE  2113536
#define OFF_LN     2146304
#define OFF_WP     18923520
#define OFF_WR     18956288
#define OFF_WW     19087360
#define OFF_HC     19120128

// Scratch (no cudaMalloc allowed)
__device__ float g_mx[128 * G3];
__device__ float g_mh[128 * G3];
__device__ float g_iface[128 * IFC];
__device__ __align__(16) float g_fwd[BSZ * NMEM * RH];
__device__ __align__(16) float g_bwd[BSZ * NMEM * RH];

__device__ __forceinline__ float sigmoidf_(float x) { return 1.f / (1.f + expf(-x)); }
__device__ __forceinline__ float softplusf_(float x) { return fmaxf(x, 0.f) + log1pf(expf(-fabsf(x))); }

// Block reductions for 512 threads (16 warps)
__device__ __forceinline__ float blk_red_sum(float v, float* sb, int t) {
#pragma unroll
    for (int o = 16; o; o >>= 1) v += __shfl_xor_sync(0xffffffffu, v, o);
    __syncthreads();
    if ((t & 31) == 0) sb[t >> 5] = v;
    __syncthreads();
    float r = 0.f;
#pragma unroll
    for (int i = 0; i < 16; i++) r += sb[i];
    return r;
}
__device__ __forceinline__ float blk_red_prod(float v, float* sb, int t) {
#pragma unroll
    for (int o = 16; o; o >>= 1) v *= __shfl_xor_sync(0xffffffffu, v, o);
    __syncthreads();
    if ((t & 31) == 0) sb[t >> 5] = v;
    __syncthreads();
    float r = 1.f;
#pragma unroll
    for (int i = 0; i < 16; i++) r *= sb[i];
    return r;
}
__device__ __forceinline__ float4 blk_red_sum4(float4 v, float4* sb, int t) {
#pragma unroll
    for (int o = 16; o; o >>= 1) {
        v.x += __shfl_xor_sync(0xffffffffu, v.x, o);
        v.y += __shfl_xor_sync(0xffffffffu, v.y, o);
        v.z += __shfl_xor_sync(0xffffffffu, v.z, o);
        v.w += __shfl_xor_sync(0xffffffffu, v.w, o);
    }
    __syncthreads();
    if ((t & 31) == 0) sb[t >> 5] = v;
    __syncthreads();
    float4 r = sb[0];
#pragma unroll
    for (int i = 1; i < 16; i++) {
        float4 s = sb[i];
        r.x += s.x; r.y += s.y; r.z += s.z; r.w += s.w;
    }
    return r;
}

// ---------------------------------------------------------------------------
// Register-tiled GEMM body (32x32 tile, 128 threads, 2x4 micro),
// single-sync double-buffered (Round-13 winner).
// ---------------------------------------------------------------------------
__device__ __forceinline__ void gemm_body(const float* __restrict__ A,
                                          const float* __restrict__ B,
                                          const float* __restrict__ bias,
                                          float* __restrict__ C,
                                          int N, int K) {
    __shared__ __align__(16) float Ast[2][32][34];
    __shared__ __align__(16) float Bs[2][32][32];
    int t = threadIdx.x;            // 128 threads
    int m0 = blockIdx.y * 32;
    int n0 = blockIdx.x * 32;
    if (n0 >= N) return;
    int tx = t & 7;
    int ty = t >> 3;
    float acc[2][4] = {{0.f,0.f,0.f,0.f},{0.f,0.f,0.f,0.f}};
    int nkt = (K + 31) / 32;

    // preload tile 0 straight into smem buffer 0
#pragma unroll
    for (int i = 0; i < 8; i++) {
        int e = t + i * 128;
        int k = e & 31, m = e >> 5;
        Ast[0][k][m] = (k < K) ? A[(m0 + m) * K + k] : 0.f;
    }
#pragma unroll
    for (int i = 0; i < 8; i++) {
        int e = t + i * 128;
        int c = e & 31, k = e >> 5;
        Bs[0][k][c] = (k < K && n0 + c < N) ? B[k * N + n0 + c] : 0.f;
    }
    __syncthreads();

    float ra[8], rb[8];
    for (int kt = 0; kt < nkt; kt++) {
        int cur = kt & 1;
        bool more = (kt + 1 < nkt);
        if (more) {
            int k0n = (kt + 1) * 32;
#pragma unroll
            for (int i = 0; i < 8; i++) {
                int e = t + i * 128;
                int k = e & 31, m = e >> 5;
                ra[i] = (k0n + k < K) ? A[(m0 + m) * K + k0n + k] : 0.f;
            }
#pragma unroll
            for (int i = 0; i < 8; i++) {
                int e = t + i * 128;
                int c = e & 31, k = e >> 5;
                rb[i] = (k0n + k < K && n0 + c < N) ? B[(k0n + k) * N + n0 + c] : 0.f;
            }
        }
#pragma unroll
        for (int kk = 0; kk < 32; kk++) {
            float2 a2 = *(const float2*)&Ast[cur][kk][ty * 2];
            float4 b4 = *(const float4*)&Bs[cur][kk][tx * 4];
            acc[0][0] += a2.x * b4.x; acc[0][1] += a2.x * b4.y;
            acc[0][2] += a2.x * b4.z; acc[0][3] += a2.x * b4.w;
            acc[1][0] += a2.y * b4.x; acc[1][1] += a2.y * b4.y;
            acc[1][2] += a2.y * b4.z; acc[1][3] += a2.y * b4.w;
        }
        if (more) {
            int nxt = cur ^ 1;
#pragma unroll
            for (int i = 0; i < 8; i++) {
                int e = t + i * 128;
                Ast[nxt][e & 31][e >> 5] = ra[i];
            }
#pragma unroll
            for (int i = 0; i < 8; i++) {
                int e = t + i * 128;
                Bs[nxt][e >> 5][e & 31] = rb[i];
            }
            __syncthreads();
        }
    }
#pragma unroll
    for (int i = 0; i < 2; i++) {
        int row = m0 + ty * 2 + i;
#pragma unroll
        for (int j = 0; j < 4; j++) {
            int col = n0 + tx * 4 + j;
            if (col < N) {
                float v = acc[i][j];
                if (bias) v += bias[col];
                C[row * N + col] = v;
            }
        }
    }
}

__global__ void gemm_gru(const float* __restrict__ X, const float* __restrict__ H,
                         const float* __restrict__ gk, const float* __restrict__ grk,
                         const float* __restrict__ gb) {
    if (blockIdx.z == 0) gemm_body(X, gk, gb, g_mx, G3, IND);
    else                 gemm_body(H, grk, gb + G3, g_mh, G3, CD);
}

__global__ void gemm_iface(const float* __restrict__ hc, const float* __restrict__ Wif) {
    gemm_body(hc, Wif, nullptr, g_iface, IFC, CD);
}

// ---------------------------------------------------------------------------
// GRU combine: c = z*h + (1-z)*gelu(xh + r*rh)
// Also zeroes the fwd/bwd atomic accumulators for this launch.
// ---------------------------------------------------------------------------
__global__ void gru_combine(const float* __restrict__ h, float* __restrict__ hc_out) {
    int idx = blockIdx.x * blockDim.x + threadIdx.x;
    // zero g_fwd / g_bwd (BSZ*NMEM*RH = 131072 floats = 32768 float4 each)
    if (idx < 32768) {
        ((float4*)g_fwd)[idx] = make_float4(0.f, 0.f, 0.f, 0.f);
        ((float4*)g_bwd)[idx] = make_float4(0.f, 0.f, 0.f, 0.f);
    }
    if (idx >= 128 * CD) return;
    int row = idx / CD, j = idx % CD;
    const float* mx = g_mx + row * G3;
    const float* mh = g_mh + row * G3;
    float z = sigmoidf_(mx[j] + mh[j]);
    float r = sigmoidf_(mx[CD + j] + mh[CD + j]);
    float hin = mx[2 * CD + j] + r * mh[2 * CD + j];
    float hh = hin * normcdff(hin);   // exact gelu
    float hv = h[idx];
    hc_out[idx] = z * hv + (1.f - z) * hh;
}

// ---------------------------------------------------------------------------
// Fused memory update: grid (2, 64) x 512 threads.
// No-max softmax (scores bounded); Wp prefetched at top.
// ---------------------------------------------------------------------------
__global__ void memupdate_kernel(const float* __restrict__ W_read,
                                 const float* __restrict__ W_write,
                                 const float* __restrict__ usage,
                                 const float* __restrict__ M,
                                 const float* __restrict__ Wp,
                                 float* __restrict__ usage_out,
                                 float* __restrict__ Ww_out,
                                 float* __restrict__ Wp_out) {
    __shared__ __align__(16) float us[NMEM];
    __shared__ float ps[NMEM];
    __shared__ float es[NMEM];
    __shared__ __align__(16) float ks[WD];
    __shared__ float sb[16];
    int b = blockIdx.y, h = blockIdx.x, t = threadIdx.x;   // 512 threads
    int tt = t & 255;
    int np = h * 256 + tt;
    const float* ifw = g_iface + (2 * b + 1) * IFC;

    // 1) issue long-latency loads immediately
    float4 mreg[16];
    {
        const float4* m4p = (const float4*)(M + (b * NMEM + t) * WD);
#pragma unroll
        for (int i = 0; i < 16; i++) mreg[i] = m4p[i];
    }
    float wpv = Wp[b * NMEM + np];     // prefetch precedence

    // 2) usage for global row t
    float4 wr4 = *(const float4*)(W_read + (b * NMEM + t) * RH);
    float ret = (1.f - sigmoidf_(ifw[453]) * wr4.x)
              * (1.f - sigmoidf_(ifw[454]) * wr4.y)
              * (1.f - sigmoidf_(ifw[455]) * wr4.z)
              * (1.f - sigmoidf_(ifw[456]) * wr4.w);
    float u = usage[b * NMEM + t], w = W_write[b * NMEM + t];
    float un = (u + w - u * w) * ret;
    us[t] = un;
    if ((t >> 8) == h) usage_out[b * NMEM + t] = un;
    if (t < WD) ks[t] = ifw[260 + t];

    // 3) interface scalars, per-thread (broadcast loads)
    float bw = 1.f + softplusf_(ifw[324]);
    float ag = sigmoidf_(ifw[457]);
    float wg = sigmoidf_(ifw[458]);

    // 4) memory-row norm from registers
    float nrm = 0.f;
#pragma unroll
    for (int i = 0; i < 16; i++) {
        float4 m4 = mreg[i];
        nrm += m4.x * m4.x + m4.y * m4.y + m4.z * m4.z + m4.w * m4.w;
    }
    __syncthreads();   // publish us, ks

    // 5) raw dot + key norm (redundant per-thread)
    float dot = 0.f, ksum = 0.f;
    {
        const float4* ks4 = (const float4*)ks;
#pragma unroll
        for (int i = 0; i < 16; i++) {
            float4 m4 = mreg[i];
            float4 k4 = ks4[i];
            dot  += m4.x * k4.x + m4.y * k4.y + m4.z * k4.z + m4.w * k4.w;
            ksum += k4.x * k4.x + k4.y * k4.y + k4.z * k4.z + k4.w * k4.w;
        }
    }
    float s = dot * (1.f / sqrtf(fmaxf(nrm, 1e-12f)))
                  * (1.f / sqrtf(fmaxf(ksum, 1e-12f))) * bw;

    // 6) alloc half-product for row np (strict-less; 4 ILP chains)
    float unp = us[np];
    {
        float p0 = 1.f, p1 = 1.f, p2 = 1.f, p3 = 1.f;
        const float4* us4 = (const float4*)us;
        int i0 = (t >> 8) * 64;
#pragma unroll 4
        for (int i = i0; i < i0 + 64; i++) {
            float4 u4 = us4[i];
            p0 *= (u4.x < unp) ? u4.x : 1.f;
            p1 *= (u4.y < unp) ? u4.y : 1.f;
            p2 *= (u4.z < unp) ? u4.z : 1.f;
            p3 *= (u4.w < unp) ? u4.w : 1.f;
        }
        ps[t] = (p0 * p1) * (p2 * p3);
    }

    // 7) reductions: prod, then sum (no-max softmax; s bounded)
    float P = blk_red_prod(un, sb, t);
    float e = expf(s);
    es[t] = e;
    float ssum = blk_red_sum(e, sb, t);   // barriers publish ps, es

    if (t < 256) {
        float wl = es[np] / ssum;
        float walloc = (1.f - unp) * ps[t] * ps[t + 256];
        float ww = wg * (ag * walloc + (1.f - ag) * wl);
        Ww_out[b * NMEM + np] = ww;
        float wsum = wg * (ag * (1.f - P) + (1.f - ag));
        Wp_out[b * NMEM + np] = (1.f - wsum) * wpv + ww;
    }
}

// ---------------------------------------------------------------------------
// Link update + fused fwd/bwd via atomics (x 0..63) + M_n chunks (x 64..67).
// grid (68, 64), block 256
// ---------------------------------------------------------------------------
__global__ void link_kernel(const float* __restrict__ L, const float* __restrict__ Ww,
                            const float* __restrict__ Wp, const float* __restrict__ Wr,
                            const float* __restrict__ M, float* __restrict__ Mn_out,
                            float* __restrict__ Ln_out) {
    __shared__ __align__(16) float Ln_s[64][68];
    __shared__ float Wwi[64], Wwj[64], Wpj[64];
    __shared__ float Wri[64][4], Wrj[64][4];
    int b = blockIdx.y;
    int t = threadIdx.x;

    if (blockIdx.x >= 64) {
        // ---- M_n chunk: 128 rows of this batch; M prefetched first ----
        int n0 = (blockIdx.x - 64) * 128;
        const float* ifw = g_iface + (2 * b + 1) * IFC;
        const float4* M4 = (const float4*)(M + (b * NMEM + n0) * WD);
        float4 mreg[8];
#pragma unroll
        for (int i = 0; i < 8; i++) mreg[i] = M4[t + i * 256];
        float* es_ = &Ln_s[0][0];          // 64
        float* vs_ = &Ln_s[1][0];          // 64
        float* wws_ = &Ln_s[2][0];         // 128
        if (t < WD) { es_[t] = sigmoidf_(ifw[325 + t]); vs_[t] = ifw[389 + t]; }
        if (t >= 64 && t < 192) wws_[t - 64] = Ww[b * NMEM + n0 + t - 64];
        __syncthreads();
        float4* Mn4 = (float4*)(Mn_out + (b * NMEM + n0) * WD);
#pragma unroll
        for (int i = 0; i < 8; i++) {
            int idx4 = t + i * 256;
            int n = idx4 >> 4, w4 = (idx4 & 15) * 4;
            float wwn = wws_[n];
            float4 m4 = mreg[i];
            float4 o;
            o.x = m4.x * (1.f - wwn * es_[w4 + 0]) + wwn * vs_[w4 + 0];
            o.y = m4.y * (1.f - wwn * es_[w4 + 1]) + wwn * vs_[w4 + 1];
            o.z = m4.z * (1.f - wwn * es_[w4 + 2]) + wwn * vs_[w4 + 2];
            o.w = m4.w * (1.f - wwn * es_[w4 + 3]) + wwn * vs_[w4 + 3];
            Mn4[idx4] = o;
        }
        return;
    }

    int it = blockIdx.x >> 3, jt = blockIdx.x & 7;
    int i0 = it * 64, j0 = jt * 64;
    if (t < 64) {
        Wwi[t] = Ww[b * NMEM + i0 + t];
        Wwj[t] = Ww[b * NMEM + j0 + t];
        Wpj[t] = Wp[b * NMEM + j0 + t];
    }
    {
        int n = t >> 2, r = t & 3;
        Wri[n][r] = Wr[(b * NMEM + i0 + n) * RH + r];
        Wrj[n][r] = Wr[(b * NMEM + j0 + n) * RH + r];
    }
    __syncthreads();
#pragma unroll
    for (int k = 0; k < 4; k++) {
        int e4 = t + k * 256;
        int il = e4 >> 4, j4 = (e4 & 15) * 4;
        long gidx = ((long)(b * NMEM + i0 + il)) * NMEM + j0 + j4;
        float4 l4 = *(const float4*)(L + gidx);
        float wwi = Wwi[il];
        float4 ln;
        ln.x = (1.f - wwi - Wwj[j4 + 0]) * l4.x + wwi * Wpj[j4 + 0];
        ln.y = (1.f - wwi - Wwj[j4 + 1]) * l4.y + wwi * Wpj[j4 + 1];
        ln.z = (1.f - wwi - Wwj[j4 + 2]) * l4.z + wwi * Wpj[j4 + 2];
        ln.w = (1.f - wwi - Wwj[j4 + 3]) * l4.w + wwi * Wpj[j4 + 3];
        if (it == jt) {
            if (il == j4 + 0) ln.x = 0.f;
            if (il == j4 + 1) ln.y = 0.f;
            if (il == j4 + 2) ln.z = 0.f;
            if (il == j4 + 3) ln.w = 0.f;
        }
        *(float4*)&Ln_s[il][j4] = ln;
        *(float4*)(Ln_out + gidx) = ln;
    }
    __syncthreads();
    {
        int il = t >> 2, r = t & 3;
        float accF = 0.f, accB = 0.f;
#pragma unroll
        for (int c = 0; c < 64; c++) {
            accF += Ln_s[il][c] * Wrj[c][r];
            accB += Ln_s[c][il] * Wri[c][r];
        }
        atomicAdd(&g_fwd[(b * NMEM + i0 + il) * RH + r], accF);
        atomicAdd(&g_bwd[(b * NMEM + j0 + il) * RH + r], accB);
    }
}

// ---------------------------------------------------------------------------
// Fused: read content lookup + mode mix -> Wr_n + read vectors + y.
// 64 blocks x 512 threads.
// ---------------------------------------------------------------------------
__global__ void read_fused_kernel(const float* __restrict__ Mn,
                                  const float* __restrict__ Wro,
                                  float* __restrict__ Wr_out,
                                  float* __restrict__ y_out) {
    __shared__ __align__(16) float fwd_s[NMEM * RH];
    __shared__ __align__(16) float bwd_s[NMEM * RH];
    __shared__ float Wrs[NMEM][RH];
    __shared__ __align__(16) float nk[RH][WD];   // RAW keys
    __shared__ float br[RH];
    __shared__ float m0s[RH], m1s[RH], m2s[RH];
    __shared__ __align__(16) float4 sb4[16];
    __shared__ __align__(16) float4 partf[512];  // 8KB
    __shared__ __align__(16) float rv[256];
    __shared__ float party[512];
    int b = blockIdx.x, t = threadIdx.x;
    const float* ifr = g_iface + (2 * b) * IFC;

    // load fwd/bwd accumulators (1 float4 each per thread)
    {
        ((float4*)fwd_s)[t] = ((const float4*)(g_fwd + b * NMEM * RH))[t];
        ((float4*)bwd_s)[t] = ((const float4*)(g_bwd + b * NMEM * RH))[t];
    }
    if (t < RH * WD) {
        int r = t >> 6, w = t & 63;
        nk[r][w] = ifr[r * WD + w];   // raw, no normalization
    }
    if (t >= 256 && t < 256 + RH) {
        int r = t - 256;
        br[r] = 1.f + softplusf_(ifr[256 + r]);
        float a = ifr[459 + r], bb = ifr[463 + r], c = ifr[467 + r];
        float mx = fmaxf(a, fmaxf(bb, c));
        float ea = expf(a - mx), eb = expf(bb - mx), ec = expf(c - mx);
        float s = ea + eb + ec;
        m0s[r] = ea / s; m1s[r] = eb / s; m2s[r] = ec / s;
    }
    __syncthreads();

    // content lookup: raw dots + redundant per-thread key norms
    const float4* m4p = (const float4*)(Mn + (b * NMEM + t) * WD);
    float d[RH] = {0.f, 0.f, 0.f, 0.f};
    float kn[RH] = {0.f, 0.f, 0.f, 0.f};
    float nrm = 0.f;
#pragma unroll
    for (int i = 0; i < 16; i++) {
        float4 m4 = m4p[i];
        nrm += m4.x * m4.x + m4.y * m4.y + m4.z * m4.z + m4.w * m4.w;
#pragma unroll
        for (int r = 0; r < RH; r++) {
            float4 k4 = ((const float4*)nk[r])[i];
            d[r]  += m4.x * k4.x + m4.y * k4.y + m4.z * k4.z + m4.w * k4.w;
            kn[r] += k4.x * k4.x + k4.y * k4.y + k4.z * k4.z + k4.w * k4.w;
        }
    }
    float rn = 1.f / sqrtf(fmaxf(nrm, 1e-12f));
    // no-max softmax (bounded scores)
    float4 e4 = make_float4(
        expf(d[0] * rn * (1.f / sqrtf(fmaxf(kn[0], 1e-12f))) * br[0]),
        expf(d[1] * rn * (1.f / sqrtf(fmaxf(kn[1], 1e-12f))) * br[1]),
        expf(d[2] * rn * (1.f / sqrtf(fmaxf(kn[2], 1e-12f))) * br[2]),
        expf(d[3] * rn * (1.f / sqrtf(fmaxf(kn[3], 1e-12f))) * br[3]));
    float4 sum4 = blk_red_sum4(e4, sb4, t);
    float wl[RH] = {e4.x / sum4.x, e4.y / sum4.y, e4.z / sum4.z, e4.w / sum4.w};

#pragma unroll
    for (int r = 0; r < RH; r++) {
        float v = m0s[r] * bwd_s[t * RH + r] + m1s[r] * wl[r] + m2s[r] * fwd_s[t * RH + r];
        Wr_out[(b * NMEM + t) * RH + r] = v;
        Wrs[t][r] = v;
    }
    __syncthreads();

    // read vectors (float4): thread = (slice=t>>6, r=(t>>4)&3, w4=t&15)
    {
        int slice = t >> 6, r = (t >> 4) & 3, w4 = t & 15;
        int n0 = slice * 64;
        float4 acc = make_float4(0.f, 0.f, 0.f, 0.f);
        const float4* Mn4 = (const float4*)(Mn + (b * NMEM + n0) * WD);
#pragma unroll 8
        for (int n = 0; n < 64; n++) {
            float4 m4 = Mn4[n * 16 + w4];
            float wr = Wrs[n0 + n][r];
            acc.x += m4.x * wr; acc.y += m4.y * wr;
            acc.z += m4.z * wr; acc.w += m4.w * wr;
        }
        partf[t] = acc;
    }
    __syncthreads();
    if (t < 64) {   // reduce 8 slices -> rv[r*64 + w]
        int r = t >> 4, w4 = t & 15;
        float4 s = make_float4(0.f, 0.f, 0.f, 0.f);
#pragma unroll
        for (int sl = 0; sl < 8; sl++) {
            float4 p = partf[sl * 64 + t];
            s.x += p.x; s.y += p.y; s.z += p.z; s.w += p.w;
        }
        *(float4*)&rv[r * 64 + w4 * 4] = s;
    }
    __syncthreads();
    // y = rv @ W_read_out ; all 512 threads (k-split)
    {
        int half = t >> 8, tt = t & 255;
        int k0 = half * 128;
        float ya = 0.f;
#pragma unroll 8
        for (int k = 0; k < 128; k++) ya += rv[k0 + k] * Wro[(k0 + k) * OUTD + tt];
        party[t] = ya;
    }
    __syncthreads();
    if (t < 256) y_out[b * OUTD + t] = party[t] + party[256 + t];
}

// ---------------------------------------------------------------------------
extern "C" void kernel_launch(void* const* d_in, const int* in_sizes, int n_in,
                              void* d_out, int out_size) {
    const float* inputs   = (const float*)d_in[0];
    const float* M        = (const float*)d_in[1];
    const float* usage    = (const float*)d_in[2];
    const float* L        = (const float*)d_in[3];
    const float* Wp       = (const float*)d_in[4];
    const float* W_read   = (const float*)d_in[5];
    const float* W_write  = (const float*)d_in[6];
    const float* h_ctrl   = (const float*)d_in[7];
    const float* W_iface  = (const float*)d_in[8];
    const float* W_rdout  = (const float*)d_in[9];
    const float* gru_k    = (const float*)d_in[10];
    const float* gru_rk   = (const float*)d_in[11];
    const float* gru_b    = (const float*)d_in[12];

    float* out = (float*)d_out;
    float* o_y    = out + OFF_Y;
    float* o_mn   = out + OFF_MN;
    float* o_use  = out + OFF_USAGE;
    float* o_ln   = out + OFF_LN;
    float* o_wp   = out + OFF_WP;
    float* o_wr   = out + OFF_WR;
    float* o_ww   = out + OFF_WW;
    float* o_hc   = out + OFF_HC;

    // 1) GRU mats mx & mh in one launch (double-buffered 32x32 tiles)
    gemm_gru<<<dim3((G3 + 31) / 32, 4, 2), 128>>>(inputs, h_ctrl, gru_k, gru_rk, gru_b);
    // 2) combine -> hc ; zero fwd/bwd accumulators
    gru_combine<<<(128 * CD + 255) / 256, 256>>>(h_ctrl, o_hc);
    // 3) interface = hc @ W_interface
    gemm_iface<<<dim3((IFC + 31) / 32, 4), 128>>>(o_hc, W_iface);
    // 4) fused usage + alloc + write lookup + Ww + Wp
    memupdate_kernel<<<dim3(2, BSZ), 512>>>(W_read, W_write, usage, M, Wp,
                                            o_use, o_ww, o_wp);
    // 5) link update + fwd/bwd atomics + M_n chunks
    link_kernel<<<dim3(68, BSZ), 256>>>(L, o_ww, Wp, W_read, M, o_mn, o_ln);
    // 6) fused read lookup + Wr + read vectors + y
    read_fused_kernel<<<BSZ, NMEM>>>(o_mn, W_rdout, o_wr, o_y);
}

// round 17
// speedup vs baseline: 1.2276x; 1.1053x over previous
#include <cuda_runtime.h>
#include <math.h>

// Problem dims
#define BSZ   64
#define NMEM  512
#define WD    64
#define RH    4
#define OUTD  256
#define IND   256
#define IFC   471     // interface size
#define CD    727     // controller dim
#define G3    2181    // 3*CD

// Output layout offsets (concatenated flattened tuple, f32)
#define OFF_Y      0
#define OFF_MN     16384
#define OFF_USAGE  2113536
#define OFF_LN     2146304
#define OFF_WP     18923520
#define OFF_WR     18956288
#define OFF_WW     19087360
#define OFF_HC     19120128

// Scratch (no cudaMalloc allowed)
__device__ float g_mx[128 * G3];
__device__ float g_mh[128 * G3];
__device__ float g_iface[128 * IFC];
__device__ __align__(16) float g_fwd[BSZ * NMEM * RH];
__device__ __align__(16) float g_bwd[BSZ * NMEM * RH];

__device__ __forceinline__ float sigmoidf_(float x) { return 1.f / (1.f + expf(-x)); }
__device__ __forceinline__ float softplusf_(float x) { return fmaxf(x, 0.f) + log1pf(expf(-fabsf(x))); }

__device__ __forceinline__ unsigned tf32_(float v) {
    unsigned r;
    asm("cvt.rna.tf32.f32 %0, %1;" : "=r"(r) : "f"(v));
    return r;
}
__device__ __forceinline__ void mma_tf32(float& c0, float& c1, float& c2, float& c3,
                                         unsigned a0, unsigned a1, unsigned a2, unsigned a3,
                                         unsigned b0, unsigned b1) {
    asm volatile("mma.sync.aligned.m16n8k8.row.col.f32.tf32.tf32.f32 "
                 "{%0,%1,%2,%3}, {%4,%5,%6,%7}, {%8,%9}, {%0,%1,%2,%3};"
                 : "+f"(c0), "+f"(c1), "+f"(c2), "+f"(c3)
                 : "r"(a0), "r"(a1), "r"(a2), "r"(a3), "r"(b0), "r"(b1));
}

// Block reductions for 512 threads (16 warps)
__device__ __forceinline__ float blk_red_sum(float v, float* sb, int t) {
#pragma unroll
    for (int o = 16; o; o >>= 1) v += __shfl_xor_sync(0xffffffffu, v, o);
    __syncthreads();
    if ((t & 31) == 0) sb[t >> 5] = v;
    __syncthreads();
    float r = 0.f;
#pragma unroll
    for (int i = 0; i < 16; i++) r += sb[i];
    return r;
}
__device__ __forceinline__ float blk_red_prod(float v, float* sb, int t) {
#pragma unroll
    for (int o = 16; o; o >>= 1) v *= __shfl_xor_sync(0xffffffffu, v, o);
    __syncthreads();
    if ((t & 31) == 0) sb[t >> 5] = v;
    __syncthreads();
    float r = 1.f;
#pragma unroll
    for (int i = 0; i < 16; i++) r *= sb[i];
    return r;
}
__device__ __forceinline__ float4 blk_red_sum4(float4 v, float4* sb, int t) {
#pragma unroll
    for (int o = 16; o; o >>= 1) {
        v.x += __shfl_xor_sync(0xffffffffu, v.x, o);
        v.y += __shfl_xor_sync(0xffffffffu, v.y, o);
        v.z += __shfl_xor_sync(0xffffffffu, v.z, o);
        v.w += __shfl_xor_sync(0xffffffffu, v.w, o);
    }
    __syncthreads();
    if ((t & 31) == 0) sb[t >> 5] = v;
    __syncthreads();
    float4 r = sb[0];
#pragma unroll
    for (int i = 1; i < 16; i++) {
        float4 s = sb[i];
        r.x += s.x; r.y += s.y; r.z += s.z; r.w += s.w;
    }
    return r;
}

// ---------------------------------------------------------------------------
// tf32 tensor-core GEMM body: 32x32 block tile, 128 threads (4 warps, 2x2),
// double-buffered single-sync pipeline, fp32 accumulate.
// ---------------------------------------------------------------------------
__device__ __forceinline__ void gemm_body(const float* __restrict__ A,
                                          const float* __restrict__ B,
                                          const float* __restrict__ bias,
                                          float* __restrict__ C,
                                          int N, int K) {
    __shared__ unsigned As[2][32][36];   // [m][k], stride 36: conflict-free frags
    __shared__ unsigned Bs[2][32][36];   // [k][n]
    int t = threadIdx.x;
    int m0 = blockIdx.y * 32, n0 = blockIdx.x * 32;
    if (n0 >= N) return;
    int warp = t >> 5, lane = t & 31;
    int g = lane >> 2, tig = lane & 3;
    int wr = (warp & 1) * 16, wc = (warp >> 1) * 16;
    float c[2][4] = {{0.f,0.f,0.f,0.f},{0.f,0.f,0.f,0.f}};
    int nkt = (K + 31) / 32;

    // preload tile 0
#pragma unroll
    for (int i = 0; i < 8; i++) {
        int e = t + i * 128;
        int k = e & 31, m = e >> 5;
        As[0][m][k] = tf32_((k < K) ? A[(m0 + m) * K + k] : 0.f);
    }
#pragma unroll
    for (int i = 0; i < 8; i++) {
        int e = t + i * 128;
        int cc = e & 31, k = e >> 5;
        Bs[0][k][cc] = tf32_((k < K && n0 + cc < N) ? B[k * N + n0 + cc] : 0.f);
    }
    __syncthreads();

    float ra[8], rb[8];
    for (int kt = 0; kt < nkt; kt++) {
        int cur = kt & 1;
        bool more = (kt + 1 < nkt);
        if (more) {
            int k0n = (kt + 1) * 32;
#pragma unroll
            for (int i = 0; i < 8; i++) {
                int e = t + i * 128;
                int k = e & 31, m = e >> 5;
                ra[i] = (k0n + k < K) ? A[(m0 + m) * K + k0n + k] : 0.f;
            }
#pragma unroll
            for (int i = 0; i < 8; i++) {
                int e = t + i * 128;
                int cc = e & 31, k = e >> 5;
                rb[i] = (k0n + k < K && n0 + cc < N) ? B[(k0n + k) * N + n0 + cc] : 0.f;
            }
        }
        // compute: 4 k8 chunks, 2 n8 tiles per warp
#pragma unroll
        for (int kc = 0; kc < 4; kc++) {
            int kb = kc * 8;
            unsigned a0 = As[cur][wr + g][kb + tig];
            unsigned a1 = As[cur][wr + g + 8][kb + tig];
            unsigned a2 = As[cur][wr + g][kb + tig + 4];
            unsigned a3 = As[cur][wr + g + 8][kb + tig + 4];
#pragma unroll
            for (int nt = 0; nt < 2; nt++) {
                unsigned b0 = Bs[cur][kb + tig][wc + nt * 8 + g];
                unsigned b1 = Bs[cur][kb + tig + 4][wc + nt * 8 + g];
                mma_tf32(c[nt][0], c[nt][1], c[nt][2], c[nt][3],
                         a0, a1, a2, a3, b0, b1);
            }
        }
        if (more) {
            int nxt = cur ^ 1;
#pragma unroll
            for (int i = 0; i < 8; i++) {
                int e = t + i * 128;
                As[nxt][e >> 5][e & 31] = tf32_(ra[i]);
            }
#pragma unroll
            for (int i = 0; i < 8; i++) {
                int e = t + i * 128;
                Bs[nxt][e >> 5][e & 31] = tf32_(rb[i]);
            }
            __syncthreads();
        }
    }
    // epilogue: c[nt] -> rows (m0+wr+g, +8), cols (n0+wc+nt*8+tig*2, +1)
#pragma unroll
    for (int nt = 0; nt < 2; nt++) {
        int col0 = n0 + wc + nt * 8 + tig * 2;
        int r0 = m0 + wr + g, r1 = r0 + 8;
        if (col0 < N) {
            float bv = bias ? bias[col0] : 0.f;
            C[r0 * N + col0] = c[nt][0] + bv;
            C[r1 * N + col0] = c[nt][2] + bv;
        }
        if (col0 + 1 < N) {
            float bv = bias ? bias[col0 + 1] : 0.f;
            C[r0 * N + col0 + 1] = c[nt][1] + bv;
            C[r1 * N + col0 + 1] = c[nt][3] + bv;
        }
    }
}

__global__ void gemm_gru(const float* __restrict__ X, const float* __restrict__ H,
                         const float* __restrict__ gk, const float* __restrict__ grk,
                         const float* __restrict__ gb) {
    if (blockIdx.z == 0) gemm_body(X, gk, gb, g_mx, G3, IND);
    else                 gemm_body(H, grk, gb + G3, g_mh, G3, CD);
}

__global__ void gemm_iface(const float* __restrict__ hc, const float* __restrict__ Wif) {
    gemm_body(hc, Wif, nullptr, g_iface, IFC, CD);
}

// ---------------------------------------------------------------------------
// GRU combine: c = z*h + (1-z)*gelu(xh + r*rh)
// Also zeroes the fwd/bwd atomic accumulators for this launch.
// ---------------------------------------------------------------------------
__global__ void gru_combine(const float* __restrict__ h, float* __restrict__ hc_out) {
    int idx = blockIdx.x * blockDim.x + threadIdx.x;
    if (idx < 32768) {
        ((float4*)g_fwd)[idx] = make_float4(0.f, 0.f, 0.f, 0.f);
        ((float4*)g_bwd)[idx] = make_float4(0.f, 0.f, 0.f, 0.f);
    }
    if (idx >= 128 * CD) return;
    int row = idx / CD, j = idx % CD;
    const float* mx = g_mx + row * G3;
    const float* mh = g_mh + row * G3;
    float z = sigmoidf_(mx[j] + mh[j]);
    float r = sigmoidf_(mx[CD + j] + mh[CD + j]);
    float hin = mx[2 * CD + j] + r * mh[2 * CD + j];
    float hh = hin * normcdff(hin);   // exact gelu
    float hv = h[idx];
    hc_out[idx] = z * hv + (1.f - z) * hh;
}

// ---------------------------------------------------------------------------
// Fused memory update: grid (2, 64) x 512 threads.
// ---------------------------------------------------------------------------
__global__ void memupdate_kernel(const float* __restrict__ W_read,
                                 const float* __restrict__ W_write,
                                 const float* __restrict__ usage,
                                 const float* __restrict__ M,
                                 const float* __restrict__ Wp,
                                 float* __restrict__ usage_out,
                                 float* __restrict__ Ww_out,
                                 float* __restrict__ Wp_out) {
    __shared__ __align__(16) float us[NMEM];
    __shared__ float ps[NMEM];
    __shared__ float es[NMEM];
    __shared__ __align__(16) float ks[WD];
    __shared__ float sb[16];
    int b = blockIdx.y, h = blockIdx.x, t = threadIdx.x;   // 512 threads
    int tt = t & 255;
    int np = h * 256 + tt;
    const float* ifw = g_iface + (2 * b + 1) * IFC;

    // 1) issue long-latency loads immediately
    float4 mreg[16];
    {
        const float4* m4p = (const float4*)(M + (b * NMEM + t) * WD);
#pragma unroll
        for (int i = 0; i < 16; i++) mreg[i] = m4p[i];
    }
    float wpv = Wp[b * NMEM + np];     // prefetch precedence

    // 2) usage for global row t
    float4 wr4 = *(const float4*)(W_read + (b * NMEM + t) * RH);
    float ret = (1.f - sigmoidf_(ifw[453]) * wr4.x)
              * (1.f - sigmoidf_(ifw[454]) * wr4.y)
              * (1.f - sigmoidf_(ifw[455]) * wr4.z)
              * (1.f - sigmoidf_(ifw[456]) * wr4.w);
    float u = usage[b * NMEM + t], w = W_write[b * NMEM + t];
    float un = (u + w - u * w) * ret;
    us[t] = un;
    if ((t >> 8) == h) usage_out[b * NMEM + t] = un;
    if (t < WD) ks[t] = ifw[260 + t];

    // 3) interface scalars, per-thread (broadcast loads)
    float bw = 1.f + softplusf_(ifw[324]);
    float ag = sigmoidf_(ifw[457]);
    float wg = sigmoidf_(ifw[458]);

    // 4) memory-row norm from registers
    float nrm = 0.f;
#pragma unroll
    for (int i = 0; i < 16; i++) {
        float4 m4 = mreg[i];
        nrm += m4.x * m4.x + m4.y * m4.y + m4.z * m4.z + m4.w * m4.w;
    }
    __syncthreads();   // publish us, ks

    // 5) raw dot + key norm (redundant per-thread)
    float dot = 0.f, ksum = 0.f;
    {
        const float4* ks4 = (const float4*)ks;
#pragma unroll
        for (int i = 0; i < 16; i++) {
            float4 m4 = mreg[i];
            float4 k4 = ks4[i];
            dot  += m4.x * k4.x + m4.y * k4.y + m4.z * k4.z + m4.w * k4.w;
            ksum += k4.x * k4.x + k4.y * k4.y + k4.z * k4.z + k4.w * k4.w;
        }
    }
    float s = dot * (1.f / sqrtf(fmaxf(nrm, 1e-12f)))
                  * (1.f / sqrtf(fmaxf(ksum, 1e-12f))) * bw;

    // 6) alloc half-product for row np (strict-less; 4 ILP chains)
    float unp = us[np];
    {
        float p0 = 1.f, p1 = 1.f, p2 = 1.f, p3 = 1.f;
        const float4* us4 = (const float4*)us;
        int i0 = (t >> 8) * 64;
#pragma unroll 4
        for (int i = i0; i < i0 + 64; i++) {
            float4 u4 = us4[i];
            p0 *= (u4.x < unp) ? u4.x : 1.f;
            p1 *= (u4.y < unp) ? u4.y : 1.f;
            p2 *= (u4.z < unp) ? u4.z : 1.f;
            p3 *= (u4.w < unp) ? u4.w : 1.f;
        }
        ps[t] = (p0 * p1) * (p2 * p3);
    }

    // 7) reductions: prod, then sum (no-max softmax; s bounded)
    float P = blk_red_prod(un, sb, t);
    float e = expf(s);
    es[t] = e;
    float ssum = blk_red_sum(e, sb, t);   // barriers publish ps, es

    if (t < 256) {
        float wl = es[np] / ssum;
        float walloc = (1.f - unp) * ps[t] * ps[t + 256];
        float ww = wg * (ag * walloc + (1.f - ag) * wl);
        Ww_out[b * NMEM + np] = ww;
        float wsum = wg * (ag * (1.f - P) + (1.f - ag));
        Wp_out[b * NMEM + np] = (1.f - wsum) * wpv + ww;
    }
}

// ---------------------------------------------------------------------------
// Link update + fused fwd/bwd via atomics (x 0..63) + M_n chunks (x 64..67).
// grid (68, 64), block 256
// ---------------------------------------------------------------------------
__global__ void link_kernel(const float* __restrict__ L, const float* __restrict__ Ww,
                            const float* __restrict__ Wp, const float* __restrict__ Wr,
                            const float* __restrict__ M, float* __restrict__ Mn_out,
                            float* __restrict__ Ln_out) {
    __shared__ __align__(16) float Ln_s[64][68];
    __shared__ float Wwi[64], Wwj[64], Wpj[64];
    __shared__ float Wri[64][4], Wrj[64][4];
    int b = blockIdx.y;
    int t = threadIdx.x;

    if (blockIdx.x >= 64) {
        // ---- M_n chunk: 128 rows of this batch; M prefetched first ----
        int n0 = (blockIdx.x - 64) * 128;
        const float* ifw = g_iface + (2 * b + 1) * IFC;
        const float4* M4 = (const float4*)(M + (b * NMEM + n0) * WD);
        float4 mreg[8];
#pragma unroll
        for (int i = 0; i < 8; i++) mreg[i] = M4[t + i * 256];
        float* es_ = &Ln_s[0][0];          // 64
        float* vs_ = &Ln_s[1][0];          // 64
        float* wws_ = &Ln_s[2][0];         // 128
        if (t < WD) { es_[t] = sigmoidf_(ifw[325 + t]); vs_[t] = ifw[389 + t]; }
        if (t >= 64 && t < 192) wws_[t - 64] = Ww[b * NMEM + n0 + t - 64];
        __syncthreads();
        float4* Mn4 = (float4*)(Mn_out + (b * NMEM + n0) * WD);
#pragma unroll
        for (int i = 0; i < 8; i++) {
            int idx4 = t + i * 256;
            int n = idx4 >> 4, w4 = (idx4 & 15) * 4;
            float wwn = wws_[n];
            float4 m4 = mreg[i];
            float4 o;
            o.x = m4.x * (1.f - wwn * es_[w4 + 0]) + wwn * vs_[w4 + 0];
            o.y = m4.y * (1.f - wwn * es_[w4 + 1]) + wwn * vs_[w4 + 1];
            o.z = m4.z * (1.f - wwn * es_[w4 + 2]) + wwn * vs_[w4 + 2];
            o.w = m4.w * (1.f - wwn * es_[w4 + 3]) + wwn * vs_[w4 + 3];
            Mn4[idx4] = o;
        }
        return;
    }

    int it = blockIdx.x >> 3, jt = blockIdx.x & 7;
    int i0 = it * 64, j0 = jt * 64;
    if (t < 64) {
        Wwi[t] = Ww[b * NMEM + i0 + t];
        Wwj[t] = Ww[b * NMEM + j0 + t];
        Wpj[t] = Wp[b * NMEM + j0 + t];
    }
    {
        int n = t >> 2, r = t & 3;
        Wri[n][r] = Wr[(b * NMEM + i0 + n) * RH + r];
        Wrj[n][r] = Wr[(b * NMEM + j0 + n) * RH + r];
    }
    __syncthreads();
#pragma unroll
    for (int k = 0; k < 4; k++) {
        int e4 = t + k * 256;
        int il = e4 >> 4, j4 = (e4 & 15) * 4;
        long gidx = ((long)(b * NMEM + i0 + il)) * NMEM + j0 + j4;
        float4 l4 = *(const float4*)(L + gidx);
        float wwi = Wwi[il];
        float4 ln;
        ln.x = (1.f - wwi - Wwj[j4 + 0]) * l4.x + wwi * Wpj[j4 + 0];
        ln.y = (1.f - wwi - Wwj[j4 + 1]) * l4.y + wwi * Wpj[j4 + 1];
        ln.z = (1.f - wwi - Wwj[j4 + 2]) * l4.z + wwi * Wpj[j4 + 2];
        ln.w = (1.f - wwi - Wwj[j4 + 3]) * l4.w + wwi * Wpj[j4 + 3];
        if (it == jt) {
            if (il == j4 + 0) ln.x = 0.f;
            if (il == j4 + 1) ln.y = 0.f;
            if (il == j4 + 2) ln.z = 0.f;
            if (il == j4 + 3) ln.w = 0.f;
        }
        *(float4*)&Ln_s[il][j4] = ln;
        *(float4*)(Ln_out + gidx) = ln;
    }
    __syncthreads();
    {
        int il = t >> 2, r = t & 3;
        float accF = 0.f, accB = 0.f;
#pragma unroll
        for (int c = 0; c < 64; c++) {
            accF += Ln_s[il][c] * Wrj[c][r];
            accB += Ln_s[c][il] * Wri[c][r];
        }
        atomicAdd(&g_fwd[(b * NMEM + i0 + il) * RH + r], accF);
        atomicAdd(&g_bwd[(b * NMEM + j0 + il) * RH + r], accB);
    }
}

// ---------------------------------------------------------------------------
// Fused: read content lookup + mode mix -> Wr_n + read vectors + y.
// 64 blocks x 512 threads.
// ---------------------------------------------------------------------------
__global__ void read_fused_kernel(const float* __restrict__ Mn,
                                  const float* __restrict__ Wro,
                                  float* __restrict__ Wr_out,
                                  float* __restrict__ y_out) {
    __shared__ __align__(16) float fwd_s[NMEM * RH];
    __shared__ __align__(16) float bwd_s[NMEM * RH];
    __shared__ float Wrs[NMEM][RH];
    __shared__ __align__(16) float nk[RH][WD];   // RAW keys
    __shared__ float br[RH];
    __shared__ float m0s[RH], m1s[RH], m2s[RH];
    __shared__ __align__(16) float4 sb4[16];
    __shared__ __align__(16) float4 partf[512];  // 8KB
    __shared__ __align__(16) float rv[256];
    __shared__ float party[512];
    int b = blockIdx.x, t = threadIdx.x;
    const float* ifr = g_iface + (2 * b) * IFC;

    // prefetch this thread's Mn row (used for content lookup)
    float4 mreg[16];
    {
        const float4* m4p = (const float4*)(Mn + (b * NMEM + t) * WD);
#pragma unroll
        for (int i = 0; i < 16; i++) mreg[i] = m4p[i];
    }

    // load fwd/bwd accumulators (1 float4 each per thread)
    {
        ((float4*)fwd_s)[t] = ((const float4*)(g_fwd + b * NMEM * RH))[t];
        ((float4*)bwd_s)[t] = ((const float4*)(g_bwd + b * NMEM * RH))[t];
    }
    if (t < RH * WD) {
        int r = t >> 6, w = t & 63;
        nk[r][w] = ifr[r * WD + w];   // raw, no normalization
    }
    if (t >= 256 && t < 256 + RH) {
        int r = t - 256;
        br[r] = 1.f + softplusf_(ifr[256 + r]);
        float a = ifr[459 + r], bb = ifr[463 + r], c = ifr[467 + r];
        float mx = fmaxf(a, fmaxf(bb, c));
        float ea = expf(a - mx), eb = expf(bb - mx), ec = expf(c - mx);
        float s = ea + eb + ec;
        m0s[r] = ea / s; m1s[r] = eb / s; m2s[r] = ec / s;
    }
    __syncthreads();

    // content lookup: raw dots + redundant per-thread key norms
    float d[RH] = {0.f, 0.f, 0.f, 0.f};
    float kn[RH] = {0.f, 0.f, 0.f, 0.f};
    float nrm = 0.f;
#pragma unroll
    for (int i = 0; i < 16; i++) {
        float4 m4 = mreg[i];
        nrm += m4.x * m4.x + m4.y * m4.y + m4.z * m4.z + m4.w * m4.w;
#pragma unroll
        for (int r = 0; r < RH; r++) {
            float4 k4 = ((const float4*)nk[r])[i];
            d[r]  += m4.x * k4.x + m4.y * k4.y + m4.z * k4.z + m4.w * k4.w;
            kn[r] += k4.x * k4.x + k4.y * k4.y + k4.z * k4.z + k4.w * k4.w;
        }
    }
    float rn = 1.f / sqrtf(fmaxf(nrm, 1e-12f));
    // no-max softmax (bounded scores)
    float4 e4 = make_float4(
        expf(d[0] * rn * (1.f / sqrtf(fmaxf(kn[0], 1e-12f))) * br[0]),
        expf(d[1] * rn * (1.f / sqrtf(fmaxf(kn[1], 1e-12f))) * br[1]),
        expf(d[2] * rn * (1.f / sqrtf(fmaxf(kn[2], 1e-12f))) * br[2]),
        expf(d[3] * rn * (1.f / sqrtf(fmaxf(kn[3], 1e-12f))) * br[3]));
    float4 sum4 = blk_red_sum4(e4, sb4, t);
    float wl[RH] = {e4.x / sum4.x, e4.y / sum4.y, e4.z / sum4.z, e4.w / sum4.w};

#pragma unroll
    for (int r = 0; r < RH; r++) {
        float v = m0s[r] * bwd_s[t * RH + r] + m1s[r] * wl[r] + m2s[r] * fwd_s[t * RH + r];
        Wr_out[(b * NMEM + t) * RH + r] = v;
        Wrs[t][r] = v;
    }
    __syncthreads();

    // read vectors (float4): thread = (slice=t>>6, r=(t>>4)&3, w4=t&15)
    {
        int slice = t >> 6, r = (t >> 4) & 3, w4 = t & 15;
        int n0 = slice * 64;
        float4 acc = make_float4(0.f, 0.f, 0.f, 0.f);
        const float4* Mn4 = (const float4*)(Mn + (b * NMEM + n0) * WD);
#pragma unroll 8
        for (int n = 0; n < 64; n++) {
            float4 m4 = Mn4[n * 16 + w4];
            float wr = Wrs[n0 + n][r];
            acc.x += m4.x * wr; acc.y += m4.y * wr;
            acc.z += m4.z * wr; acc.w += m4.w * wr;
        }
        partf[t] = acc;
    }
    __syncthreads();
    if (t < 64) {   // reduce 8 slices -> rv[r*64 + w]
        int r = t >> 4, w4 = t & 15;
        float4 s = make_float4(0.f, 0.f, 0.f, 0.f);
#pragma unroll
        for (int sl = 0; sl < 8; sl++) {
            float4 p = partf[sl * 64 + t];
            s.x += p.x; s.y += p.y; s.z += p.z; s.w += p.w;
        }
        *(float4*)&rv[r * 64 + w4 * 4] = s;
    }
    __syncthreads();
    // y = rv @ W_read_out ; all 512 threads (k-split)
    {
        int half = t >> 8, tt = t & 255;
        int k0 = half * 128;
        float ya = 0.f;
#pragma unroll 8
        for (int k = 0; k < 128; k++) ya += rv[k0 + k] * Wro[(k0 + k) * OUTD + tt];
        party[t] = ya;
    }
    __syncthreads();
    if (t < 256) y_out[b * OUTD + t] = party[t] + party[256 + t];
}

// ---------------------------------------------------------------------------
extern "C" void kernel_launch(void* const* d_in, const int* in_sizes, int n_in,
                              void* d_out, int out_size) {
    const float* inputs   = (const float*)d_in[0];
    const float* M        = (const float*)d_in[1];
    const float* usage    = (const float*)d_in[2];
    const float* L        = (const float*)d_in[3];
    const float* Wp       = (const float*)d_in[4];
    const float* W_read   = (const float*)d_in[5];
    const float* W_write  = (const float*)d_in[6];
    const float* h_ctrl   = (const float*)d_in[7];
    const float* W_iface  = (const float*)d_in[8];
    const float* W_rdout  = (const float*)d_in[9];
    const float* gru_k    = (const float*)d_in[10];
    const float* gru_rk   = (const float*)d_in[11];
    const float* gru_b    = (const float*)d_in[12];

    float* out = (float*)d_out;
    float* o_y    = out + OFF_Y;
    float* o_mn   = out + OFF_MN;
    float* o_use  = out + OFF_USAGE;
    float* o_ln   = out + OFF_LN;
    float* o_wp   = out + OFF_WP;
    float* o_wr   = out + OFF_WR;
    float* o_ww   = out + OFF_WW;
    float* o_hc   = out + OFF_HC;

    // 1) GRU mats mx & mh in one launch (tf32 mma, double-buffered)
    gemm_gru<<<dim3((G3 + 31) / 32, 4, 2), 128>>>(inputs, h_ctrl, gru_k, gru_rk, gru_b);
    // 2) combine -> hc ; zero fwd/bwd accumulators
    gru_combine<<<(128 * CD + 255) / 256, 256>>>(h_ctrl, o_hc);
    // 3) interface = hc @ W_interface (tf32 mma)
    gemm_iface<<<dim3((IFC + 31) / 32, 4), 128>>>(o_hc, W_iface);
    // 4) fused usage + alloc + write lookup + Ww + Wp
    memupdate_kernel<<<dim3(2, BSZ), 512>>>(W_read, W_write, usage, M, Wp,
                                            o_use, o_ww, o_wp);
    // 5) link update + fwd/bwd atomics + M_n chunks
    link_kernel<<<dim3(68, BSZ), 256>>>(L, o_ww, Wp, W_read, M, o_mn, o_ln);
    // 6) fused read lookup + Wr + read vectors + y
    read_fused_kernel<<<BSZ, NMEM>>>(o_mn, W_rdout, o_wr, o_y);
}